// round 4
// baseline (speedup 1.0000x reference)
#include <cuda_runtime.h>
#include <cuda_bf16.h>
#include <cstdint>

#define BSZ  2
#define SEQ  192
#define DIN  1024
#define DD   128
#define BS   384            // BSZ*SEQ
#define N2   36864          // SEQ*SEQ
#define N3   7077888        // SEQ^3
#define OUTW 14155776       // BSZ*N3  (one output head)

// -------- scratch (device globals: allocation-free) --------
__device__ float g_P[3 * BS * DD];                           // p, sh, st (fp32)
__device__ float g_S2[2][(size_t)BSZ * N3];                  // cop scratch x2
__device__ unsigned short g_Yth[3][BSZ * DD * SEQ];          // Y^T hi [sel][b][j][y]
__device__ unsigned short g_Ytl[3][BSZ * DD * SEQ];          // Y^T lo
__device__ unsigned short g_T6h[6][(size_t)BS * DD * DD];    // T hi [head][bz][i][j]
__device__ unsigned short g_T6l[6][(size_t)BS * DD * DD];
__device__ unsigned short g_M6h[6][(size_t)BS * SEQ * DD];   // M1 hi [head][bz][x][j]
__device__ unsigned short g_M6l[6][(size_t)BS * SEQ * DD];

__constant__ int c_xsel[6] = {1, 1, 1, 2, 0, 0};
__constant__ int c_zsel[6] = {0, 0, 0, 0, 1, 2};
__constant__ int c_ysel[6] = {2, 2, 1, 2, 0, 0};
// stage3 jobs: {head, ti, tj, mode}; mode 0=plain, 1=sym offdiag, 2=sym diag
__constant__ int c_jobs[19][4] = {
    {0,0,0,2},{0,0,1,1},{0,1,1,2},
    {1,0,0,2},{1,0,1,1},{1,1,1,2},
    {2,0,0,2},{2,0,1,1},{2,1,1,2},
    {3,0,0,2},{3,0,1,1},{3,1,1,2},
    {4,0,0,0},{4,0,1,0},{4,1,0,0},{4,1,1,0},
    {5,0,0,2},{5,0,1,1},{5,1,1,2}};

// ======================= helpers =======================
__device__ __forceinline__ uint32_t smem_to_u32(const void* p) {
    uint32_t a;
    asm("{ .reg .u64 t; cvta.to.shared.u64 t, %1; cvt.u32.u64 %0, t; }" : "=r"(a) : "l"(p));
    return a;
}
__device__ __forceinline__ void ldsm4(uint32_t* r, uint32_t a) {
    asm volatile("ldmatrix.sync.aligned.m8n8.x4.shared.b16 {%0,%1,%2,%3}, [%4];"
        : "=r"(r[0]), "=r"(r[1]), "=r"(r[2]), "=r"(r[3]) : "r"(a));
}
__device__ __forceinline__ void ldsm2t(uint32_t* r, uint32_t a) {
    asm volatile("ldmatrix.sync.aligned.m8n8.x2.trans.shared.b16 {%0,%1}, [%2];"
        : "=r"(r[0]), "=r"(r[1]) : "r"(a));
}
__device__ __forceinline__ void mma16816(float* c, const uint32_t* a, const uint32_t* b) {
    asm volatile("mma.sync.aligned.m16n8k16.row.col.f32.bf16.bf16.f32 "
        "{%0,%1,%2,%3},{%4,%5,%6,%7},{%8,%9},{%0,%1,%2,%3};"
        : "+f"(c[0]), "+f"(c[1]), "+f"(c[2]), "+f"(c[3])
        : "r"(a[0]), "r"(a[1]), "r"(a[2]), "r"(a[3]), "r"(b[0]), "r"(b[1]));
}
__device__ __forceinline__ uint32_t pack_hl(float a, float b, uint32_t& lo_out) {
    __nv_bfloat16 ha = __float2bfloat16(a), hb = __float2bfloat16(b);
    float ra = a - __bfloat162float(ha), rb = b - __bfloat162float(hb);
    __nv_bfloat16 la = __float2bfloat16(ra), lb = __float2bfloat16(rb);
    lo_out = (uint32_t)__bfloat16_as_ushort(la) | ((uint32_t)__bfloat16_as_ushort(lb) << 16);
    return (uint32_t)__bfloat16_as_ushort(ha) | ((uint32_t)__bfloat16_as_ushort(hb) << 16);
}
__device__ __forceinline__ void pack8(const float* __restrict__ src, uint4& hv, uint4& lv) {
    uint32_t h[4], l[4];
    #pragma unroll
    for (int e = 0; e < 4; e++) {
        float2 f = *(const float2*)(src + 2 * e);
        h[e] = pack_hl(f.x, f.y, l[e]);
    }
    hv = make_uint4(h[0], h[1], h[2], h[3]);
    lv = make_uint4(l[0], l[1], l[2], l[3]);
}

// warp GEMM: C[MF*16 x NF*8] += A(hi/lo) @ B(hi/lo), bf16 3-term split
// A smem: rows x (ARB bytes, 16B chunks swizzled c^(r&7))
// B smem: k-rows x (BRB bytes, same swizzle), KK k-chunks of 16
template<int MF, int NF, int ARB, int BRB, int KK>
__device__ __forceinline__ void wgemm(uint32_t aH, uint32_t aL,
                                      uint32_t bH, uint32_t bL,
                                      int m0, int n0, int lane,
                                      float C[MF][NF][4])
{
    for (int kk = 0; kk < KK; kk++) {
        uint32_t ah[MF][4], al[MF][4];
        #pragma unroll
        for (int mf = 0; mf < MF; mf++) {
            int r = m0 + mf * 16 + (lane & 15);
            int ck = kk * 2 + (lane >> 4);
            uint32_t off = (uint32_t)(r * ARB + ((ck ^ (r & 7)) << 4));
            ldsm4(ah[mf], aH + off);
            ldsm4(al[mf], aL + off);
        }
        int rb = kk * 16 + (lane & 15);
        #pragma unroll
        for (int nf = 0; nf < NF; nf++) {
            int nc = (n0 >> 3) + nf;
            uint32_t boff = (uint32_t)(rb * BRB + ((nc ^ (rb & 7)) << 4));
            uint32_t bh[2], bl[2];
            ldsm2t(bh, bH + boff);
            ldsm2t(bl, bL + boff);
            #pragma unroll
            for (int mf = 0; mf < MF; mf++) {
                mma16816(C[mf][nf], ah[mf], bh);
                mma16816(C[mf][nf], al[mf], bh);
                mma16816(C[mf][nf], ah[mf], bl);
            }
        }
    }
}

// =======================================================================
// MLP (unchanged)
// =======================================================================
__global__ void k_mlp(const float* __restrict__ x,
                      const float* __restrict__ W0, const float* __restrict__ b0,
                      const float* __restrict__ W1, const float* __restrict__ b1,
                      const float* __restrict__ W2, const float* __restrict__ b2)
{
    int mat = blockIdx.y;
    const float* W  = (mat == 0) ? W0 : (mat == 1) ? W1 : W2;
    const float* bb = (mat == 0) ? b0 : (mat == 1) ? b1 : b2;
    float* out = g_P + (size_t)mat * BS * DD;
    int row0 = blockIdx.x * 32;
    const float* A = x + (size_t)row0 * DIN;
    __shared__ float xs[32][32];
    __shared__ float ws[32][128];
    int t = threadIdx.x;
    int cx = t & 31, ry = t >> 5;
    float acc[4][4] = {};
    for (int kc = 0; kc < DIN; kc += 32) {
        #pragma unroll
        for (int u = 0; u < 4; u++) {
            int idx = t + u * 256;
            xs[idx >> 5][idx & 31] = A[(idx >> 5) * DIN + kc + (idx & 31)];
        }
        #pragma unroll
        for (int u = 0; u < 16; u++) {
            int idx = t + u * 256;
            ws[idx >> 7][idx & 127] = W[(kc + (idx >> 7)) * DD + (idx & 127)];
        }
        __syncthreads();
        #pragma unroll
        for (int k = 0; k < 32; k++) {
            float4 wv = *(const float4*)&ws[k][cx * 4];
            #pragma unroll
            for (int m = 0; m < 4; m++) {
                float av = xs[ry * 4 + m][k];
                acc[m][0] += av * wv.x; acc[m][1] += av * wv.y;
                acc[m][2] += av * wv.z; acc[m][3] += av * wv.w;
            }
        }
        __syncthreads();
    }
    float4 bv = *(const float4*)&bb[cx * 4];
    #pragma unroll
    for (int m = 0; m < 4; m++) {
        float4 v;
        v.x = acc[m][0] + bv.x; v.y = acc[m][1] + bv.y;
        v.z = acc[m][2] + bv.z; v.w = acc[m][3] + bv.w;
        v.x = v.x > 0.f ? v.x : 0.1f * v.x;
        v.y = v.y > 0.f ? v.y : 0.1f * v.y;
        v.z = v.z > 0.f ? v.z : 0.1f * v.z;
        v.w = v.w > 0.f ? v.w : 0.1f * v.w;
        *(float4*)&out[(size_t)(row0 + ry * 4 + m) * DD + cx * 4] = v;
    }
}

// =======================================================================
// Y prep for ALL 3 selectors: g_P[sel][b][y][j] -> g_Yt*[sel][b][j][y]
// grid (6 ytiles, 4 jtiles, 6 = sel*2+b), block (32,8)
// =======================================================================
__global__ void k_yprep()
{
    int sel = blockIdx.z >> 1, b = blockIdx.z & 1;
    int y0 = blockIdx.x * 32, j0 = blockIdx.y * 32;
    const float* src = g_P + (size_t)sel * BS * DD + (size_t)b * SEQ * DD;
    __shared__ float t[32][33];
    int tx = threadIdx.x, ty = threadIdx.y;
    #pragma unroll
    for (int r = 0; r < 4; r++)
        t[ty + r * 8][tx] = src[(size_t)(y0 + ty + r * 8) * DD + j0 + tx];
    __syncthreads();
    #pragma unroll
    for (int r = 0; r < 4; r++) {
        int jj = ty + r * 8, yy = tx;
        float v = t[yy][jj];
        __nv_bfloat16 h = __float2bfloat16(v);
        __nv_bfloat16 l = __float2bfloat16(v - __bfloat162float(h));
        size_t o = (size_t)b * DD * SEQ + (size_t)(j0 + jj) * SEQ + y0 + yy;
        g_Yth[sel][o] = __bfloat16_as_ushort(h);
        g_Ytl[sel][o] = __bfloat16_as_ushort(l);
    }
}

// =======================================================================
// Stage1 all heads: T[h][bz,i,j] = sum_k Z[bz,k] W_h[i,k,j]
// grid (128 i, 3 bz-tiles, 6 heads), 256 threads, 64KB smem (K-chunked)
// smem: ZH@0(16K) ZL@16K WH@32K(16K) WL@48K
// =======================================================================
#define S1_SMEM 65536
__global__ void __launch_bounds__(256, 2) k_stage1_all(
    const float* __restrict__ W0, const float* __restrict__ W1,
    const float* __restrict__ W2, const float* __restrict__ W3,
    const float* __restrict__ W4, const float* __restrict__ W5)
{
    extern __shared__ __align__(16) char smem[];
    uint32_t sb = smem_to_u32(smem);
    int tid = threadIdx.x, lane = tid & 31, w = tid >> 5;
    int i = blockIdx.x, bz0 = blockIdx.y * 128, head = blockIdx.z;
    const float* W = (head == 0) ? W0 : (head == 1) ? W1 : (head == 2) ? W2
                   : (head == 3) ? W3 : (head == 4) ? W4 : W5;
    const float* Z  = g_P + (size_t)c_zsel[head] * BS * DD + (size_t)bz0 * DD;
    const float* Wi = W + (size_t)i * DD * DD;

    float C[4][4][4] = {};
    int m0 = (w >> 2) * 64, n0 = (w & 3) * 32;

    for (int kc = 0; kc < 128; kc += 64) {
        __syncthreads();
        for (int idx = tid; idx < 1024; idx += 256) {   // Z: 128 rows x 8 chunks
            int r = idx >> 3, c = idx & 7;
            uint32_t off = (uint32_t)(r * 128 + ((c ^ (r & 7)) << 4));
            uint4 hv, lv;
            pack8(Z + (size_t)r * DD + kc + c * 8, hv, lv);
            *(uint4*)(smem + off) = hv;
            *(uint4*)(smem + 16384 + off) = lv;
        }
        for (int idx = tid; idx < 1024; idx += 256) {   // W: 64 k-rows x 16 chunks
            int r = idx >> 4, c = idx & 15;
            uint32_t off = (uint32_t)(r * 256 + ((c ^ (r & 7)) << 4));
            uint4 hv, lv;
            pack8(Wi + (size_t)(kc + r) * DD + c * 8, hv, lv);
            *(uint4*)(smem + 32768 + off) = hv;
            *(uint4*)(smem + 49152 + off) = lv;
        }
        __syncthreads();
        wgemm<4, 4, 128, 256, 4>(sb, sb + 16384, sb + 32768, sb + 49152, m0, n0, lane, C);
    }

    uint32_t* TH = (uint32_t*)g_T6h[head];
    uint32_t* TL = (uint32_t*)g_T6l[head];
    #pragma unroll
    for (int mf = 0; mf < 4; mf++)
        #pragma unroll
        for (int nf = 0; nf < 4; nf++) {
            int row = m0 + mf * 16 + (lane >> 2);
            int col = n0 + nf * 8 + (lane & 3) * 2;
            uint32_t lo;
            uint32_t hi = pack_hl(C[mf][nf][0], C[mf][nf][1], lo);
            size_t o = ((size_t)(bz0 + row) * 16384 + (size_t)i * 128 + col) >> 1;
            TH[o] = hi; TL[o] = lo;
            hi = pack_hl(C[mf][nf][2], C[mf][nf][3], lo);
            o = ((size_t)(bz0 + row + 8) * 16384 + (size_t)i * 128 + col) >> 1;
            TH[o] = hi; TL[o] = lo;
        }
}

// =======================================================================
// Stage2 all heads: M1[h][bz,x,j] = sum_i X[b,x,i] T[h][bz,i,j]
// grid (3 x-chunks of 64, 384 bz, 6 heads), 256 threads, 96KB smem
// smem: XH@0(16K) XL@16K TH@32K(32K) TL@64K
// =======================================================================
#define S2_SMEM 98304
__global__ void __launch_bounds__(256, 2) k_stage2_all()
{
    extern __shared__ __align__(16) char smem[];
    uint32_t sb = smem_to_u32(smem);
    int tid = threadIdx.x, lane = tid & 31, w = tid >> 5;
    int xc = blockIdx.x, bz = blockIdx.y, head = blockIdx.z, b = bz / SEQ;

    const float* X = g_P + (size_t)c_xsel[head] * BS * DD
                   + ((size_t)b * SEQ + xc * 64) * DD;
    const uint4* TH4 = (const uint4*)(g_T6h[head] + (size_t)bz * 16384);
    const uint4* TL4 = (const uint4*)(g_T6l[head] + (size_t)bz * 16384);

    for (int idx = tid; idx < 1024; idx += 256) {    // X: 64 rows x 16 chunks
        int r = idx >> 4, c = idx & 15;
        uint32_t off = (uint32_t)(r * 256 + ((c ^ (r & 7)) << 4));
        uint4 hv, lv;
        pack8(X + (size_t)r * DD + c * 8, hv, lv);
        *(uint4*)(smem + off) = hv;
        *(uint4*)(smem + 16384 + off) = lv;
    }
    for (int idx = tid; idx < 2048; idx += 256) {    // T: 128 rows x 16 chunks
        int r = idx >> 4, c = idx & 15;
        uint32_t off = (uint32_t)(r * 256 + ((c ^ (r & 7)) << 4));
        *(uint4*)(smem + 32768 + off) = TH4[idx];
        *(uint4*)(smem + 65536 + off) = TL4[idx];
    }
    __syncthreads();

    float C[2][4][4] = {};
    int m0 = (w >> 2) * 32, n0 = (w & 3) * 32;
    wgemm<2, 4, 256, 256, 8>(sb, sb + 16384, sb + 32768, sb + 65536, m0, n0, lane, C);

    uint32_t* MH = (uint32_t*)g_M6h[head];
    uint32_t* ML = (uint32_t*)g_M6l[head];
    #pragma unroll
    for (int mf = 0; mf < 2; mf++)
        #pragma unroll
        for (int nf = 0; nf < 4; nf++) {
            int row = m0 + mf * 16 + (lane >> 2);
            int col = n0 + nf * 8 + (lane & 3) * 2;
            uint32_t lo;
            uint32_t hi = pack_hl(C[mf][nf][0], C[mf][nf][1], lo);
            size_t o = (((size_t)bz * SEQ + xc * 64 + row) * DD + col) >> 1;
            MH[o] = hi; ML[o] = lo;
            hi = pack_hl(C[mf][nf][2], C[mf][nf][3], lo);
            o = (((size_t)bz * SEQ + xc * 64 + row + 8) * DD + col) >> 1;
            MH[o] = hi; ML[o] = lo;
        }
}

// =======================================================================
// Stage3 all jobs: S tile (ti,tj) 96x96 per (job, bz); sym folded in.
// grid (19 jobs, 384 bz), 256 threads, 112KB smem
// smem: AH@0(24K) AL@24576 BH@49152(32K) BL@81920 ; Ssm reuses A region
// =======================================================================
#define S3_SMEM 114688
__global__ void __launch_bounds__(256, 2) k_stage3_all(float* __restrict__ out)
{
    extern __shared__ __align__(16) char smem[];
    uint32_t sb = smem_to_u32(smem);
    int tid = threadIdx.x, lane = tid & 31, w = tid >> 5;
    int jb = blockIdx.x, bz = blockIdx.y, b = bz / SEQ;
    int head = c_jobs[jb][0], ti = c_jobs[jb][1], tj = c_jobs[jb][2], mode = c_jobs[jb][3];

    const uint4* A4h = (const uint4*)(g_M6h[head] + ((size_t)bz * SEQ + ti * 96) * DD);
    const uint4* A4l = (const uint4*)(g_M6l[head] + ((size_t)bz * SEQ + ti * 96) * DD);
    int ysel = c_ysel[head];
    const uint4* B4h = (const uint4*)(g_Yth[ysel] + (size_t)b * DD * SEQ);
    const uint4* B4l = (const uint4*)(g_Ytl[ysel] + (size_t)b * DD * SEQ);

    for (int idx = tid; idx < 1536; idx += 256) {    // A: 96 rows x 16 chunks
        int r = idx >> 4, c = idx & 15;
        uint32_t off = (uint32_t)(r * 256 + ((c ^ (r & 7)) << 4));
        *(uint4*)(smem + off) = A4h[idx];
        *(uint4*)(smem + 24576 + off) = A4l[idx];
    }
    for (int idx = tid; idx < 1536; idx += 256) {    // B: 128 j-rows x 12 chunks
        int r = idx / 12, c = idx % 12;
        uint32_t off = (uint32_t)(r * 256 + ((c ^ (r & 7)) << 4));
        int src = r * 24 + tj * 12 + c;              // uint4 units, row stride SEQ=24 u4
        *(uint4*)(smem + 49152 + off) = B4h[src];
        *(uint4*)(smem + 81920 + off) = B4l[src];
    }
    __syncthreads();

    float C[3][3][4] = {};
    int m0 = (w >> 2) * 48, n0 = (w & 3) * 24;
    wgemm<3, 3, 256, 256, 8>(sb, sb + 24576, sb + 49152, sb + 81920, m0, n0, lane, C);
    __syncthreads();

    // frags -> Ssm (stride 97, conflict-free transposed reads)
    float* Ssm = (float*)smem;
    #pragma unroll
    for (int mf = 0; mf < 3; mf++)
        #pragma unroll
        for (int nf = 0; nf < 3; nf++) {
            int row = m0 + mf * 16 + (lane >> 2);
            int col = n0 + nf * 8 + (lane & 3) * 2;
            Ssm[row * 97 + col]           = C[mf][nf][0];
            Ssm[row * 97 + col + 1]       = C[mf][nf][1];
            Ssm[(row + 8) * 97 + col]     = C[mf][nf][2];
            Ssm[(row + 8) * 97 + col + 1] = C[mf][nf][3];
        }
    __syncthreads();

    float* dst = (head < 4) ? (out + (size_t)head * OUTW) : g_S2[head - 4];
    dst += (size_t)bz * N2;

    if (mode == 2) {                       // sym diagonal tile
        float* b1 = dst + (size_t)(ti * 96) * SEQ + ti * 96;
        for (int i2 = tid; i2 < 2304; i2 += 256) {
            int r = i2 / 24, q = (i2 % 24) * 4;
            float4 v;
            v.x = (r <= q)     ? Ssm[r * 97 + q]     : Ssm[q * 97 + r];
            v.y = (r <= q + 1) ? Ssm[r * 97 + q + 1] : Ssm[(q + 1) * 97 + r];
            v.z = (r <= q + 2) ? Ssm[r * 97 + q + 2] : Ssm[(q + 2) * 97 + r];
            v.w = (r <= q + 3) ? Ssm[r * 97 + q + 3] : Ssm[(q + 3) * 97 + r];
            *(float4*)(b1 + (size_t)r * SEQ + q) = v;
        }
    } else {
        float* b1 = dst + (size_t)(ti * 96) * SEQ + tj * 96;
        for (int i2 = tid; i2 < 2304; i2 += 256) {
            int r = i2 / 24, q = (i2 % 24) * 4;
            float4 v = make_float4(Ssm[r * 97 + q],     Ssm[r * 97 + q + 1],
                                   Ssm[r * 97 + q + 2], Ssm[r * 97 + q + 3]);
            *(float4*)(b1 + (size_t)r * SEQ + q) = v;
        }
        if (mode == 1) {                   // mirrored tile (transpose)
            float* b2 = dst + (size_t)(tj * 96) * SEQ + ti * 96;
            for (int i2 = tid; i2 < 2304; i2 += 256) {
                int r = i2 / 24, q = (i2 % 24) * 4;
                float4 v = make_float4(Ssm[q * 97 + r],       Ssm[(q + 1) * 97 + r],
                                       Ssm[(q + 2) * 97 + r], Ssm[(q + 3) * 97 + r]);
                *(float4*)(b2 + (size_t)r * SEQ + q) = v;
            }
        }
    }
}

// =======================================================================
// Permute (0,2,3,1): out[b, q=x*S+y, z] = g_S2[hs][b, z, q]
// grid (1152, 6, 4 = hs*2+b), block (32,8)
// =======================================================================
__global__ void k_perm(float* __restrict__ out)
{
    int hs = blockIdx.z >> 1, b = blockIdx.z & 1;
    const float* in = g_S2[hs] + (size_t)b * N3;
    float* o = out + (size_t)(4 + hs) * OUTW + (size_t)b * N3;
    int q0 = blockIdx.x * 32, z0 = blockIdx.y * 32;
    __shared__ float tile[32][33];
    int tx = threadIdx.x, ty = threadIdx.y;
    #pragma unroll
    for (int r = 0; r < 4; r++)
        tile[ty + r * 8][tx] = in[(size_t)(z0 + ty + r * 8) * N2 + q0 + tx];
    __syncthreads();
    #pragma unroll
    for (int r = 0; r < 4; r++)
        o[(size_t)(q0 + ty + r * 8) * SEQ + z0 + tx] = tile[tx][ty + r * 8];
}

// =======================================================================
extern "C" void kernel_launch(void* const* d_in, const int* in_sizes, int n_in,
                              void* d_out, int out_size)
{
    const float* x  = (const float*)d_in[0];
    const float* Wp = (const float*)d_in[1];
    const float* bp = (const float*)d_in[2];
    const float* Wh = (const float*)d_in[3];
    const float* bh = (const float*)d_in[4];
    const float* Wt = (const float*)d_in[5];
    const float* bt = (const float*)d_in[6];
    float* out = (float*)d_out;

    cudaFuncSetAttribute(k_stage1_all, cudaFuncAttributeMaxDynamicSharedMemorySize, S1_SMEM);
    cudaFuncSetAttribute(k_stage2_all, cudaFuncAttributeMaxDynamicSharedMemorySize, S2_SMEM);
    cudaFuncSetAttribute(k_stage3_all, cudaFuncAttributeMaxDynamicSharedMemorySize, S3_SMEM);

    k_mlp<<<dim3(12, 3), 256>>>(x, Wp, bp, Wh, bh, Wt, bt);
    k_yprep<<<dim3(6, 4, 6), dim3(32, 8)>>>();
    k_stage1_all<<<dim3(128, 3, 6), 256, S1_SMEM>>>(
        (const float*)d_in[7],  (const float*)d_in[8],  (const float*)d_in[9],
        (const float*)d_in[10], (const float*)d_in[11], (const float*)d_in[12]);
    k_stage2_all<<<dim3(3, 384, 6), 256, S2_SMEM>>>();
    k_stage3_all<<<dim3(19, 384), 256, S3_SMEM>>>(out);
    k_perm<<<dim3(1152, 6, 4), dim3(32, 8)>>>(out);
}

// round 5
// speedup vs baseline: 1.5980x; 1.5980x over previous
#include <cuda_runtime.h>
#include <cuda_bf16.h>
#include <cstdint>

#define BSZ  2
#define SEQ  192
#define DIN  1024
#define DD   128
#define BS   384            // BSZ*SEQ
#define N2   36864          // SEQ*SEQ
#define N3   7077888        // SEQ^3
#define OUTW 14155776       // BSZ*N3  (one output head)

// -------- scratch (device globals: allocation-free) --------
__device__ float g_P[3 * BS * DD];                           // p, sh, st (fp32)
__device__ float g_S2[2][(size_t)BSZ * N3];                  // cop scratch x2
__device__ unsigned short g_Pbh[3][BS * DD];                 // P bf16 hi [sel][bz][k]
__device__ unsigned short g_Pbl[3][BS * DD];                 // P bf16 lo
__device__ unsigned short g_Yth[3][BSZ * DD * SEQ];          // Y^T hi [sel][b][j][y]
__device__ unsigned short g_Ytl[3][BSZ * DD * SEQ];          // Y^T lo
__device__ unsigned short g_T6h[6][(size_t)BS * DD * DD];    // T hi [head][bz][i][j]
__device__ unsigned short g_T6l[6][(size_t)BS * DD * DD];

__constant__ int c_xsel[6] = {1, 1, 1, 2, 0, 0};
__constant__ int c_zsel[6] = {0, 0, 0, 0, 1, 2};
__constant__ int c_ysel[6] = {2, 2, 1, 2, 0, 0};
__constant__ int c_sym[6]  = {1, 1, 1, 1, 0, 1};

// ======================= helpers =======================
__device__ __forceinline__ uint32_t smem_to_u32(const void* p) {
    uint32_t a;
    asm("{ .reg .u64 t; cvta.to.shared.u64 t, %1; cvt.u32.u64 %0, t; }" : "=r"(a) : "l"(p));
    return a;
}
__device__ __forceinline__ void ldsm4(uint32_t* r, uint32_t a) {
    asm volatile("ldmatrix.sync.aligned.m8n8.x4.shared.b16 {%0,%1,%2,%3}, [%4];"
        : "=r"(r[0]), "=r"(r[1]), "=r"(r[2]), "=r"(r[3]) : "r"(a));
}
__device__ __forceinline__ void ldsm4t(uint32_t* r, uint32_t a) {
    asm volatile("ldmatrix.sync.aligned.m8n8.x4.trans.shared.b16 {%0,%1,%2,%3}, [%4];"
        : "=r"(r[0]), "=r"(r[1]), "=r"(r[2]), "=r"(r[3]) : "r"(a));
}
__device__ __forceinline__ void mma16816(float* c, const uint32_t* a, const uint32_t* b) {
    asm volatile("mma.sync.aligned.m16n8k16.row.col.f32.bf16.bf16.f32 "
        "{%0,%1,%2,%3},{%4,%5,%6,%7},{%8,%9},{%0,%1,%2,%3};"
        : "+f"(c[0]), "+f"(c[1]), "+f"(c[2]), "+f"(c[3])
        : "r"(a[0]), "r"(a[1]), "r"(a[2]), "r"(a[3]), "r"(b[0]), "r"(b[1]));
}
__device__ __forceinline__ uint32_t pack_hl(float a, float b, uint32_t& lo_out) {
    __nv_bfloat16 ha = __float2bfloat16(a), hb = __float2bfloat16(b);
    float ra = a - __bfloat162float(ha), rb = b - __bfloat162float(hb);
    __nv_bfloat16 la = __float2bfloat16(ra), lb = __float2bfloat16(rb);
    lo_out = (uint32_t)__bfloat16_as_ushort(la) | ((uint32_t)__bfloat16_as_ushort(lb) << 16);
    return (uint32_t)__bfloat16_as_ushort(ha) | ((uint32_t)__bfloat16_as_ushort(hb) << 16);
}
__device__ __forceinline__ void pack8(const float* __restrict__ src, uint4& hv, uint4& lv) {
    uint32_t h[4], l[4];
    #pragma unroll
    for (int e = 0; e < 4; e++) {
        float2 f = *(const float2*)(src + 2 * e);
        h[e] = pack_hl(f.x, f.y, l[e]);
    }
    hv = make_uint4(h[0], h[1], h[2], h[3]);
    lv = make_uint4(l[0], l[1], l[2], l[3]);
}

// warp GEMM, bf16 3-term split, x4-trans B loads (pairs of n-chunks)
// A smem: rows x ARB bytes (16B chunks swizzled c^(r&7))
// B smem: k-rows x BRB bytes (same swizzle), KK k-chunks of 16
template<int MF, int NF2, int ARB, int BRB, int KK>
__device__ __forceinline__ void wgemm(uint32_t aH, uint32_t aL,
                                      uint32_t bH, uint32_t bL,
                                      int m0, int n0, int lane,
                                      float C[MF][NF2 * 2][4])
{
    for (int kk = 0; kk < KK; kk++) {
        uint32_t ah[MF][4], al[MF][4];
        #pragma unroll
        for (int mf = 0; mf < MF; mf++) {
            int r = m0 + mf * 16 + (lane & 15);
            int ck = kk * 2 + (lane >> 4);
            uint32_t off = (uint32_t)(r * ARB + ((ck ^ (r & 7)) << 4));
            ldsm4(ah[mf], aH + off);
            ldsm4(al[mf], aL + off);
        }
        int rb = kk * 16 + (lane & 15);
        #pragma unroll
        for (int nf2 = 0; nf2 < NF2; nf2++) {
            int ncq = (n0 >> 3) + nf2 * 2 + (lane >> 4);
            uint32_t boff = (uint32_t)(rb * BRB + ((ncq ^ (rb & 7)) << 4));
            uint32_t bh[4], bl[4];
            ldsm4t(bh, bH + boff);
            ldsm4t(bl, bL + boff);
            #pragma unroll
            for (int mf = 0; mf < MF; mf++) {
                mma16816(C[mf][nf2 * 2], ah[mf], bh);
                mma16816(C[mf][nf2 * 2], al[mf], bh);
                mma16816(C[mf][nf2 * 2], ah[mf], bl);
                mma16816(C[mf][nf2 * 2 + 1], ah[mf], bh + 2);
                mma16816(C[mf][nf2 * 2 + 1], al[mf], bh + 2);
                mma16816(C[mf][nf2 * 2 + 1], ah[mf], bl + 2);
            }
        }
    }
}

// =======================================================================
// MLP (unchanged)
// =======================================================================
__global__ void k_mlp(const float* __restrict__ x,
                      const float* __restrict__ W0, const float* __restrict__ b0,
                      const float* __restrict__ W1, const float* __restrict__ b1,
                      const float* __restrict__ W2, const float* __restrict__ b2)
{
    int mat = blockIdx.y;
    const float* W  = (mat == 0) ? W0 : (mat == 1) ? W1 : W2;
    const float* bb = (mat == 0) ? b0 : (mat == 1) ? b1 : b2;
    float* out = g_P + (size_t)mat * BS * DD;
    int row0 = blockIdx.x * 32;
    const float* A = x + (size_t)row0 * DIN;
    __shared__ float xs[32][32];
    __shared__ float ws[32][128];
    int t = threadIdx.x;
    int cx = t & 31, ry = t >> 5;
    float acc[4][4] = {};
    for (int kc = 0; kc < DIN; kc += 32) {
        #pragma unroll
        for (int u = 0; u < 4; u++) {
            int idx = t + u * 256;
            xs[idx >> 5][idx & 31] = A[(idx >> 5) * DIN + kc + (idx & 31)];
        }
        #pragma unroll
        for (int u = 0; u < 16; u++) {
            int idx = t + u * 256;
            ws[idx >> 7][idx & 127] = W[(kc + (idx >> 7)) * DD + (idx & 127)];
        }
        __syncthreads();
        #pragma unroll
        for (int k = 0; k < 32; k++) {
            float4 wv = *(const float4*)&ws[k][cx * 4];
            #pragma unroll
            for (int m = 0; m < 4; m++) {
                float av = xs[ry * 4 + m][k];
                acc[m][0] += av * wv.x; acc[m][1] += av * wv.y;
                acc[m][2] += av * wv.z; acc[m][3] += av * wv.w;
            }
        }
        __syncthreads();
    }
    float4 bv = *(const float4*)&bb[cx * 4];
    #pragma unroll
    for (int m = 0; m < 4; m++) {
        float4 v;
        v.x = acc[m][0] + bv.x; v.y = acc[m][1] + bv.y;
        v.z = acc[m][2] + bv.z; v.w = acc[m][3] + bv.w;
        v.x = v.x > 0.f ? v.x : 0.1f * v.x;
        v.y = v.y > 0.f ? v.y : 0.1f * v.y;
        v.z = v.z > 0.f ? v.z : 0.1f * v.z;
        v.w = v.w > 0.f ? v.w : 0.1f * v.w;
        *(float4*)&out[(size_t)(row0 + ry * 4 + m) * DD + cx * 4] = v;
    }
}

// =======================================================================
// P prep: g_P fp32 -> g_Pbh/g_Pbl bf16 hi/lo (all 3 selectors)
// =======================================================================
__global__ void k_pprep()
{
    int idx = blockIdx.x * 1024 + threadIdx.x;    // pair index, 73728 total
    if (idx >= 3 * BS * DD / 2) return;
    int sel = idx / (BS * DD / 2);
    int p = idx % (BS * DD / 2);
    float2 f = *(const float2*)(g_P + (size_t)sel * BS * DD + p * 2);
    uint32_t lo;
    uint32_t hi = pack_hl(f.x, f.y, lo);
    ((uint32_t*)g_Pbh[sel])[p] = hi;
    ((uint32_t*)g_Pbl[sel])[p] = lo;
}

// =======================================================================
// Y prep for all 3 selectors: g_P[sel][b][y][j] -> g_Yt*[sel][b][j][y]
// grid (6 ytiles, 4 jtiles, 6 = sel*2+b), block (32,8)
// =======================================================================
__global__ void k_yprep()
{
    int sel = blockIdx.z >> 1, b = blockIdx.z & 1;
    int y0 = blockIdx.x * 32, j0 = blockIdx.y * 32;
    const float* src = g_P + (size_t)sel * BS * DD + (size_t)b * SEQ * DD;
    __shared__ float t[32][33];
    int tx = threadIdx.x, ty = threadIdx.y;
    #pragma unroll
    for (int r = 0; r < 4; r++)
        t[ty + r * 8][tx] = src[(size_t)(y0 + ty + r * 8) * DD + j0 + tx];
    __syncthreads();
    #pragma unroll
    for (int r = 0; r < 4; r++) {
        int jj = ty + r * 8, yy = tx;
        float v = t[yy][jj];
        __nv_bfloat16 h = __float2bfloat16(v);
        __nv_bfloat16 l = __float2bfloat16(v - __bfloat162float(h));
        size_t o = (size_t)b * DD * SEQ + (size_t)(j0 + jj) * SEQ + y0 + yy;
        g_Yth[sel][o] = __bfloat16_as_ushort(h);
        g_Ytl[sel][o] = __bfloat16_as_ushort(l);
    }
}

// =======================================================================
// Stage1 all heads: T[h][bz,i,j] = sum_k Z[bz,k] W_h[i,k,j]
// grid (128 i, 3 bz-tiles, 6 heads), 256 threads, 64KB smem, K-chunked
// smem: ZH@0(16K) ZL@16K WH@32K(16K) WL@48K
// =======================================================================
#define S1_SMEM 65536
__global__ void __launch_bounds__(256, 2) k_stage1_all(
    const float* __restrict__ W0, const float* __restrict__ W1,
    const float* __restrict__ W2, const float* __restrict__ W3,
    const float* __restrict__ W4, const float* __restrict__ W5)
{
    extern __shared__ __align__(16) char smem[];
    uint32_t sb = smem_to_u32(smem);
    int tid = threadIdx.x, lane = tid & 31, w = tid >> 5;
    int i = blockIdx.x, bz0 = blockIdx.y * 128, head = blockIdx.z;
    const float* W = (head == 0) ? W0 : (head == 1) ? W1 : (head == 2) ? W2
                   : (head == 3) ? W3 : (head == 4) ? W4 : W5;
    int zsel = c_zsel[head];
    const uint4* Zh4 = (const uint4*)g_Pbh[zsel] + (size_t)bz0 * 16;
    const uint4* Zl4 = (const uint4*)g_Pbl[zsel] + (size_t)bz0 * 16;
    const float* Wi = W + (size_t)i * DD * DD;

    float C[4][4][4] = {};
    int m0 = (w >> 2) * 64, n0 = (w & 3) * 32;

    for (int kc = 0; kc < 128; kc += 64) {
        __syncthreads();
        for (int idx = tid; idx < 1024; idx += 256) {   // Z: 128 rows x 8 chunks
            int r = idx >> 3, c = idx & 7;
            uint32_t off = (uint32_t)(r * 128 + ((c ^ (r & 7)) << 4));
            int src = r * 16 + (kc >> 3) + c;
            *(uint4*)(smem + off) = Zh4[src];
            *(uint4*)(smem + 16384 + off) = Zl4[src];
        }
        for (int idx = tid; idx < 1024; idx += 256) {   // W: 64 k-rows x 16 chunks
            int r = idx >> 4, c = idx & 15;
            uint32_t off = (uint32_t)(r * 256 + ((c ^ (r & 7)) << 4));
            uint4 hv, lv;
            pack8(Wi + (size_t)(kc + r) * DD + c * 8, hv, lv);
            *(uint4*)(smem + 32768 + off) = hv;
            *(uint4*)(smem + 49152 + off) = lv;
        }
        __syncthreads();
        wgemm<4, 2, 128, 256, 4>(sb, sb + 16384, sb + 32768, sb + 49152, m0, n0, lane, C);
    }

    uint32_t* TH = (uint32_t*)g_T6h[head];
    uint32_t* TL = (uint32_t*)g_T6l[head];
    #pragma unroll
    for (int mf = 0; mf < 4; mf++)
        #pragma unroll
        for (int nf = 0; nf < 4; nf++) {
            int row = m0 + mf * 16 + (lane >> 2);
            int col = n0 + nf * 8 + (lane & 3) * 2;
            uint32_t lo;
            uint32_t hi = pack_hl(C[mf][nf][0], C[mf][nf][1], lo);
            size_t o = ((size_t)(bz0 + row) * 16384 + (size_t)i * 128 + col) >> 1;
            TH[o] = hi; TL[o] = lo;
            hi = pack_hl(C[mf][nf][2], C[mf][nf][3], lo);
            o = ((size_t)(bz0 + row + 8) * 16384 + (size_t)i * 128 + col) >> 1;
            TH[o] = hi; TL[o] = lo;
        }
}

// =======================================================================
// Fused stage2+3, all heads: grid (384 bz, 6 heads), 384 threads
//   M1[x,j] = sum_i X[x,i] T[i,j];  S[x,y] = sum_j M1[x,j] Yt[j,y]
// smem: X/M1 hi@0(48K) lo@49152 ; T hi@98304(32K) lo@131072
//       Y hi@98304(48K) lo@147456 ; Ssm fp32 stride 193 @0
// =======================================================================
#define S2_XH 0
#define S2_XL 49152
#define S2_TH 98304
#define S2_TL 131072
#define S2_YH 98304
#define S2_YL 147456
#define S23_SMEM 196608
__global__ void __launch_bounds__(384, 1) k_stage23_all(float* __restrict__ out)
{
    extern __shared__ __align__(16) char smem[];
    uint32_t sb = smem_to_u32(smem);
    int tid = threadIdx.x, lane = tid & 31, w = tid >> 5;
    int bz = blockIdx.x, head = blockIdx.y, b = bz / SEQ;
    int xsel = c_xsel[head], ysel = c_ysel[head], dosym = c_sym[head];

    // ---- load X (pre-packed bf16 hi/lo, swizzled) ----
    const uint4* Xh4 = (const uint4*)g_Pbh[xsel] + (size_t)b * SEQ * 16;
    const uint4* Xl4 = (const uint4*)g_Pbl[xsel] + (size_t)b * SEQ * 16;
    for (int idx = tid; idx < 3072; idx += 384) {
        int r = idx >> 4, c = idx & 15;
        uint32_t off = (uint32_t)(r * 256 + ((c ^ (r & 7)) << 4));
        *(uint4*)(smem + S2_XH + off) = Xh4[idx];
        *(uint4*)(smem + S2_XL + off) = Xl4[idx];
    }
    // ---- load T ----
    const uint4* TH4 = (const uint4*)(g_T6h[head] + (size_t)bz * DD * DD);
    const uint4* TL4 = (const uint4*)(g_T6l[head] + (size_t)bz * DD * DD);
    for (int idx = tid; idx < 2048; idx += 384) {
        int r = idx >> 4, c = idx & 15;
        uint32_t off = (uint32_t)(r * 256 + ((c ^ (r & 7)) << 4));
        *(uint4*)(smem + S2_TH + off) = TH4[idx];
        *(uint4*)(smem + S2_TL + off) = TL4[idx];
    }
    __syncthreads();

    // ---- stage2: M1 = X @ T   (warp tile 32x64; 6x2 layout) ----
    {
        float C2[2][8][4] = {};
        int m0 = (w >> 1) * 32, n0 = (w & 1) * 64;
        wgemm<2, 4, 256, 256, 8>(sb + S2_XH, sb + S2_XL, sb + S2_TH, sb + S2_TL, m0, n0, lane, C2);
        __syncthreads();
        // store M1 hi/lo into X region
        #pragma unroll
        for (int mf = 0; mf < 2; mf++)
            #pragma unroll
            for (int nf = 0; nf < 8; nf++) {
                int row = m0 + mf * 16 + (lane >> 2);
                int col = n0 + nf * 8 + (lane & 3) * 2;
                uint32_t lo0, lo1;
                uint32_t hi0 = pack_hl(C2[mf][nf][0], C2[mf][nf][1], lo0);
                uint32_t hi1 = pack_hl(C2[mf][nf][2], C2[mf][nf][3], lo1);
                int r2 = row + 8;
                uint32_t o0 = (uint32_t)(row * 256 + (((col >> 3) ^ (row & 7)) << 4) + (col & 7) * 2);
                uint32_t o1 = (uint32_t)(r2 * 256 + (((col >> 3) ^ (r2 & 7)) << 4) + (col & 7) * 2);
                *(uint32_t*)(smem + S2_XH + o0) = hi0;
                *(uint32_t*)(smem + S2_XL + o0) = lo0;
                *(uint32_t*)(smem + S2_XH + o1) = hi1;
                *(uint32_t*)(smem + S2_XL + o1) = lo1;
            }
    }
    // ---- load Y^T (128 rows x 192 cols bf16, 24 chunks/row) into T region ----
    const uint4* YH4 = (const uint4*)(g_Yth[ysel] + (size_t)b * DD * SEQ);
    const uint4* YL4 = (const uint4*)(g_Ytl[ysel] + (size_t)b * DD * SEQ);
    for (int idx = tid; idx < 3072; idx += 384) {
        int r = idx / 24, c = idx % 24;
        uint32_t off = (uint32_t)(r * 384 + ((c ^ (r & 7)) << 4));
        *(uint4*)(smem + S2_YH + off) = YH4[idx];
        *(uint4*)(smem + S2_YL + off) = YL4[idx];
    }
    __syncthreads();

    // ---- stage3: S = M1 @ Y^T  (warp tile 48x64; 4x3 layout) ----
    float C3[3][8][4] = {};
    int m3 = (w & 3) * 48, n3 = (w >> 2) * 64;
    wgemm<3, 4, 256, 384, 8>(sb + S2_XH, sb + S2_XL, sb + S2_YH, sb + S2_YL, m3, n3, lane, C3);
    __syncthreads();

    // ---- epilogue: frags -> Ssm (stride 193), sym fold, coalesced store ----
    float* Ssm = (float*)smem;
    #pragma unroll
    for (int mf = 0; mf < 3; mf++)
        #pragma unroll
        for (int nf = 0; nf < 8; nf++) {
            int row = m3 + mf * 16 + (lane >> 2);
            int col = n3 + nf * 8 + (lane & 3) * 2;
            Ssm[row * 193 + col]           = C3[mf][nf][0];
            Ssm[row * 193 + col + 1]       = C3[mf][nf][1];
            Ssm[(row + 8) * 193 + col]     = C3[mf][nf][2];
            Ssm[(row + 8) * 193 + col + 1] = C3[mf][nf][3];
        }
    __syncthreads();

    float* dst = (head < 4) ? (out + (size_t)head * OUTW) : g_S2[head - 4];
    dst += (size_t)bz * N2;
    for (int idx = tid * 4; idx < N2; idx += 384 * 4) {
        int x = idx / SEQ, y = idx % SEQ;
        float4 v;
        if (dosym) {
            v.x = (x <= y)     ? Ssm[x * 193 + y]     : Ssm[y * 193 + x];
            v.y = (x <= y + 1) ? Ssm[x * 193 + y + 1] : Ssm[(y + 1) * 193 + x];
            v.z = (x <= y + 2) ? Ssm[x * 193 + y + 2] : Ssm[(y + 2) * 193 + x];
            v.w = (x <= y + 3) ? Ssm[x * 193 + y + 3] : Ssm[(y + 3) * 193 + x];
        } else {
            v.x = Ssm[x * 193 + y];
            v.y = Ssm[x * 193 + y + 1];
            v.z = Ssm[x * 193 + y + 2];
            v.w = Ssm[x * 193 + y + 3];
        }
        *(float4*)(dst + idx) = v;
    }
}

// =======================================================================
// Permute (0,2,3,1): out[b, q=x*S+y, z] = g_S2[hs][b, z, q]
// grid (1152, 6, 4 = hs*2+b), block (32,8)
// =======================================================================
__global__ void k_perm(float* __restrict__ out)
{
    int hs = blockIdx.z >> 1, b = blockIdx.z & 1;
    const float* in = g_S2[hs] + (size_t)b * N3;
    float* o = out + (size_t)(4 + hs) * OUTW + (size_t)b * N3;
    int q0 = blockIdx.x * 32, z0 = blockIdx.y * 32;
    __shared__ float tile[32][33];
    int tx = threadIdx.x, ty = threadIdx.y;
    #pragma unroll
    for (int r = 0; r < 4; r++)
        tile[ty + r * 8][tx] = in[(size_t)(z0 + ty + r * 8) * N2 + q0 + tx];
    __syncthreads();
    #pragma unroll
    for (int r = 0; r < 4; r++)
        o[(size_t)(q0 + ty + r * 8) * SEQ + z0 + tx] = tile[tx][ty + r * 8];
}

// =======================================================================
extern "C" void kernel_launch(void* const* d_in, const int* in_sizes, int n_in,
                              void* d_out, int out_size)
{
    const float* x  = (const float*)d_in[0];
    const float* Wp = (const float*)d_in[1];
    const float* bp = (const float*)d_in[2];
    const float* Wh = (const float*)d_in[3];
    const float* bh = (const float*)d_in[4];
    const float* Wt = (const float*)d_in[5];
    const float* bt = (const float*)d_in[6];
    float* out = (float*)d_out;

    cudaFuncSetAttribute(k_stage1_all,  cudaFuncAttributeMaxDynamicSharedMemorySize, S1_SMEM);
    cudaFuncSetAttribute(k_stage23_all, cudaFuncAttributeMaxDynamicSharedMemorySize, S23_SMEM);

    k_mlp<<<dim3(12, 3), 256>>>(x, Wp, bp, Wh, bh, Wt, bt);
    k_pprep<<<72, 1024>>>();
    k_yprep<<<dim3(6, 4, 6), dim3(32, 8)>>>();
    k_stage1_all<<<dim3(128, 3, 6), 256, S1_SMEM>>>(
        (const float*)d_in[7],  (const float*)d_in[8],  (const float*)d_in[9],
        (const float*)d_in[10], (const float*)d_in[11], (const float*)d_in[12]);
    k_stage23_all<<<dim3(384, 6), 384, S23_SMEM>>>(out);
    k_perm<<<dim3(1152, 6, 4), dim3(32, 8)>>>(out);
}

// round 6
// speedup vs baseline: 1.7189x; 1.0756x over previous
#include <cuda_runtime.h>
#include <cuda_bf16.h>
#include <cstdint>

#define BSZ  2
#define SEQ  192
#define DIN  1024
#define DD   128
#define BS   384            // BSZ*SEQ
#define N2   36864          // SEQ*SEQ
#define N3   7077888       // SEQ^3
#define OUTW 14155776       // BSZ*N3  (one output head)

// -------- scratch (device globals: allocation-free) --------
__device__ float g_P[3 * BS * DD];                           // p, sh, st (fp32)
__device__ float g_S2[2][(size_t)BSZ * N3];                  // cop scratch x2
__device__ unsigned short g_Pbh[3][BS * DD];                 // P bf16 hi [sel][bz][k]
__device__ unsigned short g_Pbl[3][BS * DD];                 // P bf16 lo
__device__ unsigned short g_Yth[3][BSZ * DD * SEQ];          // Y^T hi [sel][b][j][y]
__device__ unsigned short g_Ytl[3][BSZ * DD * SEQ];          // Y^T lo
__device__ unsigned short g_T6h[6][(size_t)BS * DD * DD];    // T hi [head][bz][i][j]
__device__ unsigned short g_T6l[6][(size_t)BS * DD * DD];
__device__ unsigned short g_W6h[6][(size_t)DD * DD * DD];    // W bf16 hi [head][i][k][j]
__device__ unsigned short g_W6l[6][(size_t)DD * DD * DD];    // W bf16 lo

__constant__ int c_xsel[6] = {1, 1, 1, 2, 0, 0};
__constant__ int c_zsel[6] = {0, 0, 0, 0, 1, 2};
__constant__ int c_ysel[6] = {2, 2, 1, 2, 0, 0};
__constant__ int c_sym[6]  = {1, 1, 1, 1, 0, 1};

// ======================= helpers =======================
__device__ __forceinline__ uint32_t smem_to_u32(const void* p) {
    uint32_t a;
    asm("{ .reg .u64 t; cvta.to.shared.u64 t, %1; cvt.u32.u64 %0, t; }" : "=r"(a) : "l"(p));
    return a;
}
__device__ __forceinline__ void ldsm4(uint32_t* r, uint32_t a) {
    asm volatile("ldmatrix.sync.aligned.m8n8.x4.shared.b16 {%0,%1,%2,%3}, [%4];"
        : "=r"(r[0]), "=r"(r[1]), "=r"(r[2]), "=r"(r[3]) : "r"(a));
}
__device__ __forceinline__ void ldsm4t(uint32_t* r, uint32_t a) {
    asm volatile("ldmatrix.sync.aligned.m8n8.x4.trans.shared.b16 {%0,%1,%2,%3}, [%4];"
        : "=r"(r[0]), "=r"(r[1]), "=r"(r[2]), "=r"(r[3]) : "r"(a));
}
__device__ __forceinline__ void mma16816(float* c, const uint32_t* a, const uint32_t* b) {
    asm volatile("mma.sync.aligned.m16n8k16.row.col.f32.bf16.bf16.f32 "
        "{%0,%1,%2,%3},{%4,%5,%6,%7},{%8,%9},{%0,%1,%2,%3};"
        : "+f"(c[0]), "+f"(c[1]), "+f"(c[2]), "+f"(c[3])
        : "r"(a[0]), "r"(a[1]), "r"(a[2]), "r"(a[3]), "r"(b[0]), "r"(b[1]));
}
__device__ __forceinline__ uint32_t pack_hl(float a, float b, uint32_t& lo_out) {
    __nv_bfloat16 ha = __float2bfloat16(a), hb = __float2bfloat16(b);
    float ra = a - __bfloat162float(ha), rb = b - __bfloat162float(hb);
    __nv_bfloat16 la = __float2bfloat16(ra), lb = __float2bfloat16(rb);
    lo_out = (uint32_t)__bfloat16_as_ushort(la) | ((uint32_t)__bfloat16_as_ushort(lb) << 16);
    return (uint32_t)__bfloat16_as_ushort(ha) | ((uint32_t)__bfloat16_as_ushort(hb) << 16);
}

// warp GEMM, bf16 3-term split, x4/x4t loads.
// A smem: rows x ARB bytes, 16B chunks swizzled c^(r&7); A k-chunk base = kbase
// B smem: local k-rows x BRB bytes (same swizzle), KK k-chunks of 16
template<int MF, int NF2, int ARB, int BRB, int KK>
__device__ __forceinline__ void wgemm(uint32_t aH, uint32_t aL,
                                      uint32_t bH, uint32_t bL,
                                      int m0, int n0, int kbase, int lane,
                                      float C[MF][NF2 * 2][4])
{
    for (int kk = 0; kk < KK; kk++) {
        uint32_t ah[MF][4], al[MF][4];
        #pragma unroll
        for (int mf = 0; mf < MF; mf++) {
            int r = m0 + mf * 16 + (lane & 15);
            int ck = kbase + kk * 2 + (lane >> 4);
            uint32_t off = (uint32_t)(r * ARB + ((ck ^ (r & 7)) << 4));
            ldsm4(ah[mf], aH + off);
            ldsm4(al[mf], aL + off);
        }
        int rb = kk * 16 + (lane & 15);
        #pragma unroll
        for (int nf2 = 0; nf2 < NF2; nf2++) {
            int ncq = (n0 >> 3) + nf2 * 2 + (lane >> 4);
            uint32_t boff = (uint32_t)(rb * BRB + ((ncq ^ (rb & 7)) << 4));
            uint32_t bh[4], bl[4];
            ldsm4t(bh, bH + boff);
            ldsm4t(bl, bL + boff);
            #pragma unroll
            for (int mf = 0; mf < MF; mf++) {
                mma16816(C[mf][nf2 * 2], ah[mf], bh);
                mma16816(C[mf][nf2 * 2], al[mf], bh);
                mma16816(C[mf][nf2 * 2], ah[mf], bl);
                mma16816(C[mf][nf2 * 2 + 1], ah[mf], bh + 2);
                mma16816(C[mf][nf2 * 2 + 1], al[mf], bh + 2);
                mma16816(C[mf][nf2 * 2 + 1], ah[mf], bl + 2);
            }
        }
    }
}

// =======================================================================
// MLP
// =======================================================================
__global__ void k_mlp(const float* __restrict__ x,
                      const float* __restrict__ W0, const float* __restrict__ b0,
                      const float* __restrict__ W1, const float* __restrict__ b1,
                      const float* __restrict__ W2, const float* __restrict__ b2)
{
    int mat = blockIdx.y;
    const float* W  = (mat == 0) ? W0 : (mat == 1) ? W1 : W2;
    const float* bb = (mat == 0) ? b0 : (mat == 1) ? b1 : b2;
    float* out = g_P + (size_t)mat * BS * DD;
    int row0 = blockIdx.x * 32;
    const float* A = x + (size_t)row0 * DIN;
    __shared__ float xs[32][32];
    __shared__ float ws[32][128];
    int t = threadIdx.x;
    int cx = t & 31, ry = t >> 5;
    float acc[4][4] = {};
    for (int kc = 0; kc < DIN; kc += 32) {
        #pragma unroll
        for (int u = 0; u < 4; u++) {
            int idx = t + u * 256;
            xs[idx >> 5][idx & 31] = A[(idx >> 5) * DIN + kc + (idx & 31)];
        }
        #pragma unroll
        for (int u = 0; u < 16; u++) {
            int idx = t + u * 256;
            ws[idx >> 7][idx & 127] = W[(kc + (idx >> 7)) * DD + (idx & 127)];
        }
        __syncthreads();
        #pragma unroll
        for (int k = 0; k < 32; k++) {
            float4 wv = *(const float4*)&ws[k][cx * 4];
            #pragma unroll
            for (int m = 0; m < 4; m++) {
                float av = xs[ry * 4 + m][k];
                acc[m][0] += av * wv.x; acc[m][1] += av * wv.y;
                acc[m][2] += av * wv.z; acc[m][3] += av * wv.w;
            }
        }
        __syncthreads();
    }
    float4 bv = *(const float4*)&bb[cx * 4];
    #pragma unroll
    for (int m = 0; m < 4; m++) {
        float4 v;
        v.x = acc[m][0] + bv.x; v.y = acc[m][1] + bv.y;
        v.z = acc[m][2] + bv.z; v.w = acc[m][3] + bv.w;
        v.x = v.x > 0.f ? v.x : 0.1f * v.x;
        v.y = v.y > 0.f ? v.y : 0.1f * v.y;
        v.z = v.z > 0.f ? v.z : 0.1f * v.z;
        v.w = v.w > 0.f ? v.w : 0.1f * v.w;
        *(float4*)&out[(size_t)(row0 + ry * 4 + m) * DD + cx * 4] = v;
    }
}

// =======================================================================
// P prep: g_P fp32 -> bf16 hi/lo
// =======================================================================
__global__ void k_pprep()
{
    int idx = blockIdx.x * 1024 + threadIdx.x;
    if (idx >= 3 * BS * DD / 2) return;
    int sel = idx / (BS * DD / 2);
    int p = idx % (BS * DD / 2);
    float2 f = *(const float2*)(g_P + (size_t)sel * BS * DD + p * 2);
    uint32_t lo;
    uint32_t hi = pack_hl(f.x, f.y, lo);
    ((uint32_t*)g_Pbh[sel])[p] = hi;
    ((uint32_t*)g_Pbl[sel])[p] = lo;
}

// =======================================================================
// W prep: 6 weight tensors fp32 -> bf16 hi/lo, layout unchanged
// grid (1024, 6), 1024 threads
// =======================================================================
__global__ void k_wprep6(const float* __restrict__ W0, const float* __restrict__ W1,
                         const float* __restrict__ W2, const float* __restrict__ W3,
                         const float* __restrict__ W4, const float* __restrict__ W5)
{
    int head = blockIdx.y;
    const float* W = (head == 0) ? W0 : (head == 1) ? W1 : (head == 2) ? W2
                   : (head == 3) ? W3 : (head == 4) ? W4 : W5;
    size_t p = (size_t)blockIdx.x * 1024 + threadIdx.x;   // pair index, 1048576 total
    float2 f = *(const float2*)(W + p * 2);
    uint32_t lo;
    uint32_t hi = pack_hl(f.x, f.y, lo);
    ((uint32_t*)g_W6h[head])[p] = hi;
    ((uint32_t*)g_W6l[head])[p] = lo;
}

// =======================================================================
// Y prep: g_P[sel][b][y][j] -> g_Yt*[sel][b][j][y]
// =======================================================================
__global__ void k_yprep()
{
    int sel = blockIdx.z >> 1, b = blockIdx.z & 1;
    int y0 = blockIdx.x * 32, j0 = blockIdx.y * 32;
    const float* src = g_P + (size_t)sel * BS * DD + (size_t)b * SEQ * DD;
    __shared__ float t[32][33];
    int tx = threadIdx.x, ty = threadIdx.y;
    #pragma unroll
    for (int r = 0; r < 4; r++)
        t[ty + r * 8][tx] = src[(size_t)(y0 + ty + r * 8) * DD + j0 + tx];
    __syncthreads();
    #pragma unroll
    for (int r = 0; r < 4; r++) {
        int jj = ty + r * 8, yy = tx;
        float v = t[yy][jj];
        __nv_bfloat16 h = __float2bfloat16(v);
        __nv_bfloat16 l = __float2bfloat16(v - __bfloat162float(h));
        size_t o = (size_t)b * DD * SEQ + (size_t)(j0 + jj) * SEQ + y0 + yy;
        g_Yth[sel][o] = __bfloat16_as_ushort(h);
        g_Ytl[sel][o] = __bfloat16_as_ushort(l);
    }
}

// =======================================================================
// Stage1: T[h][bz,i,j] = sum_k Z[bz,k] W_h[i,k,j]   (pre-packed W)
// grid (128 i, 3 bz-tiles, 6 heads), 256 threads, 64KB smem, K-chunked
// =======================================================================
#define S1_SMEM 65536
__global__ void __launch_bounds__(256, 2) k_stage1_all()
{
    extern __shared__ __align__(16) char smem[];
    uint32_t sb = smem_to_u32(smem);
    int tid = threadIdx.x, lane = tid & 31, w = tid >> 5;
    int i = blockIdx.x, bz0 = blockIdx.y * 128, head = blockIdx.z;
    int zsel = c_zsel[head];
    const uint4* Zh4 = (const uint4*)g_Pbh[zsel] + (size_t)bz0 * 16;
    const uint4* Zl4 = (const uint4*)g_Pbl[zsel] + (size_t)bz0 * 16;
    const uint4* Wh4 = (const uint4*)g_W6h[head] + (size_t)i * 2048;
    const uint4* Wl4 = (const uint4*)g_W6l[head] + (size_t)i * 2048;

    float C[4][4][4] = {};
    int m0 = (w >> 2) * 64, n0 = (w & 3) * 32;

    for (int kc = 0; kc < 128; kc += 64) {
        __syncthreads();
        for (int idx = tid; idx < 1024; idx += 256) {   // Z: 128 rows x 8 chunks
            int r = idx >> 3, c = idx & 7;
            uint32_t off = (uint32_t)(r * 128 + ((c ^ (r & 7)) << 4));
            int src = r * 16 + (kc >> 3) + c;
            *(uint4*)(smem + off) = Zh4[src];
            *(uint4*)(smem + 16384 + off) = Zl4[src];
        }
        for (int idx = tid; idx < 1024; idx += 256) {   // W: 64 k-rows x 16 chunks
            int r = idx >> 4, c = idx & 15;
            uint32_t off = (uint32_t)(r * 256 + ((c ^ (r & 7)) << 4));
            int src = (kc + r) * 16 + c;
            *(uint4*)(smem + 32768 + off) = Wh4[src];
            *(uint4*)(smem + 49152 + off) = Wl4[src];
        }
        __syncthreads();
        wgemm<4, 2, 128, 256, 4>(sb, sb + 16384, sb + 32768, sb + 49152, m0, n0, 0, lane, C);
    }

    uint32_t* TH = (uint32_t*)g_T6h[head];
    uint32_t* TL = (uint32_t*)g_T6l[head];
    #pragma unroll
    for (int mf = 0; mf < 4; mf++)
        #pragma unroll
        for (int nf = 0; nf < 4; nf++) {
            int row = m0 + mf * 16 + (lane >> 2);
            int col = n0 + nf * 8 + (lane & 3) * 2;
            uint32_t lo;
            uint32_t hi = pack_hl(C[mf][nf][0], C[mf][nf][1], lo);
            size_t o = ((size_t)(bz0 + row) * 16384 + (size_t)i * 128 + col) >> 1;
            TH[o] = hi; TL[o] = lo;
            hi = pack_hl(C[mf][nf][2], C[mf][nf][3], lo);
            o = ((size_t)(bz0 + row + 8) * 16384 + (size_t)i * 128 + col) >> 1;
            TH[o] = hi; TL[o] = lo;
        }
}

// =======================================================================
// Fused stage2+3, split-M: grid (2 ti, 384 bz, 6 head), 256 threads, 112KB
//   CTA computes x rows [ti*96, ti*96+96):
//   M1[x,j] = sum_i X[x,i] T[i,j];  S[x,y] = sum_j M1[x,j] Yt[j,y]
// smem: XM hi@0(24K) lo@24576 ; T hi@49152(32K) lo@81920
//       Y chunk (64 j-rows): hi@49152(24K) lo@73728 ; Ssm 96x193 f32 @0
// sym heads: ti=1 computes only cols 96..192 (diag tile); ti=0 writes its
// off-diag tile plus the transposed mirror.
// =======================================================================
#define XM_H 0
#define XM_L 24576
#define TB_H 49152
#define TB_L 81920
#define YB_H 49152
#define YB_L 73728
#define S23_SMEM 114688
__global__ void __launch_bounds__(256, 2) k_stage23_all(float* __restrict__ out)
{
    extern __shared__ __align__(16) char smem[];
    uint32_t sb = smem_to_u32(smem);
    int tid = threadIdx.x, lane = tid & 31, w = tid >> 5;
    int ti = blockIdx.x, bz = blockIdx.y, head = blockIdx.z, b = bz / SEQ;
    int xsel = c_xsel[head], ysel = c_ysel[head], dosym = c_sym[head];
    bool narrow = dosym && (ti == 1);

    // ---- load X rows [ti*96, +96) (pre-packed bf16 hi/lo, swizzled) ----
    const uint4* Xh4 = (const uint4*)g_Pbh[xsel] + ((size_t)b * SEQ + ti * 96) * 16;
    const uint4* Xl4 = (const uint4*)g_Pbl[xsel] + ((size_t)b * SEQ + ti * 96) * 16;
    for (int idx = tid; idx < 1536; idx += 256) {
        int r = idx >> 4, c = idx & 15;
        uint32_t off = (uint32_t)(r * 256 + ((c ^ (r & 7)) << 4));
        *(uint4*)(smem + XM_H + off) = Xh4[idx];
        *(uint4*)(smem + XM_L + off) = Xl4[idx];
    }
    // ---- load T (128x128) ----
    const uint4* TH4 = (const uint4*)(g_T6h[head] + (size_t)bz * DD * DD);
    const uint4* TL4 = (const uint4*)(g_T6l[head] + (size_t)bz * DD * DD);
    for (int idx = tid; idx < 2048; idx += 256) {
        int r = idx >> 4, c = idx & 15;
        uint32_t off = (uint32_t)(r * 256 + ((c ^ (r & 7)) << 4));
        *(uint4*)(smem + TB_H + off) = TH4[idx];
        *(uint4*)(smem + TB_L + off) = TL4[idx];
    }
    __syncthreads();

    // ---- stage2: M1 = X @ T  (8 warps, tile 48x32: 2m x 4n) ----
    {
        float C2[3][4][4] = {};
        int m0 = (w >> 2) * 48, n0 = (w & 3) * 32;
        wgemm<3, 2, 256, 256, 8>(sb + XM_H, sb + XM_L, sb + TB_H, sb + TB_L,
                                 m0, n0, 0, lane, C2);
        __syncthreads();
        // M1 -> XM region (bf16 hi/lo, same swizzle)
        #pragma unroll
        for (int mf = 0; mf < 3; mf++)
            #pragma unroll
            for (int nf = 0; nf < 4; nf++) {
                int row = m0 + mf * 16 + (lane >> 2);
                int col = n0 + nf * 8 + (lane & 3) * 2;
                uint32_t lo0, lo1;
                uint32_t hi0 = pack_hl(C2[mf][nf][0], C2[mf][nf][1], lo0);
                uint32_t hi1 = pack_hl(C2[mf][nf][2], C2[mf][nf][3], lo1);
                int r2 = row + 8;
                uint32_t o0 = (uint32_t)(row * 256 + (((col >> 3) ^ (row & 7)) << 4) + (col & 7) * 2);
                uint32_t o1 = (uint32_t)(r2 * 256 + (((col >> 3) ^ (r2 & 7)) << 4) + (col & 7) * 2);
                *(uint32_t*)(smem + XM_H + o0) = hi0;
                *(uint32_t*)(smem + XM_L + o0) = lo0;
                *(uint32_t*)(smem + XM_H + o1) = hi1;
                *(uint32_t*)(smem + XM_L + o1) = lo1;
            }
    }
    __syncthreads();

    // ---- stage3: S = M1 @ Y^T, two 64-row j-chunks of Y ----
    float C3[3][6][4] = {};
    bool act = !narrow || (w & 3) < 2;
    int m3 = (w >> 2) * 48;
    int n3 = narrow ? 96 + (w & 3) * 48 : (w & 3) * 48;
    const uint4* YH4 = (const uint4*)(g_Yth[ysel] + (size_t)b * DD * SEQ);
    const uint4* YL4 = (const uint4*)(g_Ytl[ysel] + (size_t)b * DD * SEQ);
    for (int jc = 0; jc < 2; jc++) {
        for (int idx = tid; idx < 1536; idx += 256) {   // 64 rows x 24 chunks
            int r = idx / 24, c = idx % 24;
            uint32_t off = (uint32_t)(r * 384 + ((c ^ (r & 7)) << 4));
            int src = (jc * 64 + r) * 24 + c;
            *(uint4*)(smem + YB_H + off) = YH4[src];
            *(uint4*)(smem + YB_L + off) = YL4[src];
        }
        __syncthreads();
        if (act)
            wgemm<3, 3, 256, 384, 4>(sb + XM_H, sb + XM_L, sb + YB_H, sb + YB_L,
                                     m3, n3, jc * 8, lane, C3);
        __syncthreads();
    }

    // ---- epilogue: frags -> Ssm (96 x stride 193), then folded writes ----
    float* Ssm = (float*)smem;
    if (act) {
        #pragma unroll
        for (int mf = 0; mf < 3; mf++)
            #pragma unroll
            for (int nf = 0; nf < 6; nf++) {
                int row = m3 + mf * 16 + (lane >> 2);
                int col = n3 + nf * 8 + (lane & 3) * 2;
                Ssm[row * 193 + col]           = C3[mf][nf][0];
                Ssm[row * 193 + col + 1]       = C3[mf][nf][1];
                Ssm[(row + 8) * 193 + col]     = C3[mf][nf][2];
                Ssm[(row + 8) * 193 + col + 1] = C3[mf][nf][3];
            }
    }
    __syncthreads();

    float* dst = (head < 4) ? (out + (size_t)head * OUTW) : g_S2[head - 4];
    dst += (size_t)bz * N2;

    if (!dosym) {
        // plain: write own 96 rows, full width
        for (int idx = tid * 4; idx < 96 * SEQ; idx += 1024) {
            int r = idx / SEQ, y = idx % SEQ;
            float4 v = make_float4(Ssm[r * 193 + y],     Ssm[r * 193 + y + 1],
                                   Ssm[r * 193 + y + 2], Ssm[r * 193 + y + 3]);
            *(float4*)(dst + (size_t)(ti * 96 + r) * SEQ + y) = v;
        }
    } else if (ti == 0) {
        // rows 0..95 full width, fold inside tile (0,0)
        for (int idx = tid * 4; idx < 96 * SEQ; idx += 1024) {
            int r = idx / SEQ, y = idx % SEQ;
            float4 v;
            v.x = (r <= y)     ? Ssm[r * 193 + y]     : Ssm[y * 193 + r];
            v.y = (r <= y + 1) ? Ssm[r * 193 + y + 1] : Ssm[(y + 1) * 193 + r];
            v.z = (r <= y + 2) ? Ssm[r * 193 + y + 2] : Ssm[(y + 2) * 193 + r];
            v.w = (r <= y + 3) ? Ssm[r * 193 + y + 3] : Ssm[(y + 3) * 193 + r];
            *(float4*)(dst + (size_t)r * SEQ + y) = v;
        }
        // mirror: out[96+r2][c2] = S[c2][96+r2]
        for (int idx = tid * 4; idx < 96 * 96; idx += 1024) {
            int r2 = idx / 96, c2 = idx % 96;
            float4 v = make_float4(Ssm[c2 * 193 + 96 + r2],
                                   Ssm[(c2 + 1) * 193 + 96 + r2],
                                   Ssm[(c2 + 2) * 193 + 96 + r2],
                                   Ssm[(c2 + 3) * 193 + 96 + r2]);
            *(float4*)(dst + (size_t)(96 + r2) * SEQ + c2) = v;
        }
    } else {
        // narrow diag tile: out[96+r][96+c], fold r<=c
        for (int idx = tid * 4; idx < 96 * 96; idx += 1024) {
            int r = idx / 96, c = idx % 96;
            float4 v;
            v.x = (r <= c)     ? Ssm[r * 193 + 96 + c]     : Ssm[c * 193 + 96 + r];
            v.y = (r <= c + 1) ? Ssm[r * 193 + 96 + c + 1] : Ssm[(c + 1) * 193 + 96 + r];
            v.z = (r <= c + 2) ? Ssm[r * 193 + 96 + c + 2] : Ssm[(c + 2) * 193 + 96 + r];
            v.w = (r <= c + 3) ? Ssm[r * 193 + 96 + c + 3] : Ssm[(c + 3) * 193 + 96 + r];
            *(float4*)(dst + (size_t)(96 + r) * SEQ + 96 + c) = v;
        }
    }
}

// =======================================================================
// Permute (0,2,3,1): out[b, q=x*S+y, z] = g_S2[hs][b, z, q]
// =======================================================================
__global__ void k_perm(float* __restrict__ out)
{
    int hs = blockIdx.z >> 1, b = blockIdx.z & 1;
    const float* in = g_S2[hs] + (size_t)b * N3;
    float* o = out + (size_t)(4 + hs) * OUTW + (size_t)b * N3;
    int q0 = blockIdx.x * 32, z0 = blockIdx.y * 32;
    __shared__ float tile[32][33];
    int tx = threadIdx.x, ty = threadIdx.y;
    #pragma unroll
    for (int r = 0; r < 4; r++)
        tile[ty + r * 8][tx] = in[(size_t)(z0 + ty + r * 8) * N2 + q0 + tx];
    __syncthreads();
    #pragma unroll
    for (int r = 0; r < 4; r++)
        o[(size_t)(q0 + ty + r * 8) * SEQ + z0 + tx] = tile[tx][ty + r * 8];
}

// =======================================================================
extern "C" void kernel_launch(void* const* d_in, const int* in_sizes, int n_in,
                              void* d_out, int out_size)
{
    const float* x  = (const float*)d_in[0];
    const float* Wp = (const float*)d_in[1];
    const float* bp = (const float*)d_in[2];
    const float* Wh = (const float*)d_in[3];
    const float* bh = (const float*)d_in[4];
    const float* Wt = (const float*)d_in[5];
    const float* bt = (const float*)d_in[6];
    float* out = (float*)d_out;

    cudaFuncSetAttribute(k_stage1_all,  cudaFuncAttributeMaxDynamicSharedMemorySize, S1_SMEM);
    cudaFuncSetAttribute(k_stage23_all, cudaFuncAttributeMaxDynamicSharedMemorySize, S23_SMEM);

    k_wprep6<<<dim3(1024, 6), 1024>>>(
        (const float*)d_in[7],  (const float*)d_in[8],  (const float*)d_in[9],
        (const float*)d_in[10], (const float*)d_in[11], (const float*)d_in[12]);
    k_mlp<<<dim3(12, 3), 256>>>(x, Wp, bp, Wh, bh, Wt, bt);
    k_pprep<<<72, 1024>>>();
    k_yprep<<<dim3(6, 4, 6), dim3(32, 8)>>>();
    k_stage1_all<<<dim3(128, 3, 6), 256, S1_SMEM>>>();
    k_stage23_all<<<dim3(2, 384, 6), 256, S23_SMEM>>>(out);
    k_perm<<<dim3(1152, 6, 4), dim3(32, 8)>>>(out);
}

// round 7
// speedup vs baseline: 2.0811x; 1.2107x over previous
#include <cuda_runtime.h>
#include <cuda_bf16.h>
#include <cstdint>

#define BSZ  2
#define SEQ  192
#define DIN  1024
#define DD   128
#define BS   384            // BSZ*SEQ
#define N2   36864          // SEQ*SEQ
#define N3   7077888        // SEQ^3
#define OUTW 14155776       // BSZ*N3  (one output head)

// -------- scratch (device globals: allocation-free) --------
__device__ float g_P[3 * BS * DD];                           // p, sh, st (fp32)
__device__ float g_S2[2][(size_t)BSZ * N3];                  // cop scratch x2
__device__ unsigned short g_Pbh[3][BS * DD];                 // P bf16 hi [sel][bz][k]
__device__ unsigned short g_Pbl[3][BS * DD];                 // P bf16 lo
__device__ unsigned short g_Yth[3][BSZ * DD * SEQ];          // Y^T hi [sel][b][j][y]
__device__ unsigned short g_Ytl[3][BSZ * DD * SEQ];          // Y^T lo
__device__ unsigned short g_T6h[6][(size_t)BS * DD * DD];    // T hi [head][bz][i][j]
__device__ unsigned short g_T6l[6][(size_t)BS * DD * DD];
__device__ unsigned short g_W6h[6][(size_t)DD * DD * DD];    // W bf16 hi [head][i][k][j]
__device__ unsigned short g_W6l[6][(size_t)DD * DD * DD];    // W bf16 lo

__constant__ int c_xsel[6] = {1, 1, 1, 2, 0, 0};
__constant__ int c_zsel[6] = {0, 0, 0, 0, 1, 2};
__constant__ int c_ysel[6] = {2, 2, 1, 2, 0, 0};
__constant__ int c_sym[6]  = {1, 1, 1, 1, 0, 1};

// ======================= helpers =======================
__device__ __forceinline__ uint32_t smem_to_u32(const void* p) {
    uint32_t a;
    asm("{ .reg .u64 t; cvta.to.shared.u64 t, %1; cvt.u32.u64 %0, t; }" : "=r"(a) : "l"(p));
    return a;
}
#define CP_A16(dst, src) \
    asm volatile("cp.async.cg.shared.global [%0], [%1], 16;" :: "r"(dst), "l"(src))
#define CP_COMMIT() asm volatile("cp.async.commit_group;" ::: "memory")
#define CP_WAIT0()  asm volatile("cp.async.wait_group 0;" ::: "memory")
#define CP_WAIT1()  asm volatile("cp.async.wait_group 1;" ::: "memory")

__device__ __forceinline__ void ldsm4(uint32_t* r, uint32_t a) {
    asm volatile("ldmatrix.sync.aligned.m8n8.x4.shared.b16 {%0,%1,%2,%3}, [%4];"
        : "=r"(r[0]), "=r"(r[1]), "=r"(r[2]), "=r"(r[3]) : "r"(a));
}
__device__ __forceinline__ void ldsm4t(uint32_t* r, uint32_t a) {
    asm volatile("ldmatrix.sync.aligned.m8n8.x4.trans.shared.b16 {%0,%1,%2,%3}, [%4];"
        : "=r"(r[0]), "=r"(r[1]), "=r"(r[2]), "=r"(r[3]) : "r"(a));
}
__device__ __forceinline__ void mma16816(float* c, const uint32_t* a, const uint32_t* b) {
    asm volatile("mma.sync.aligned.m16n8k16.row.col.f32.bf16.bf16.f32 "
        "{%0,%1,%2,%3},{%4,%5,%6,%7},{%8,%9},{%0,%1,%2,%3};"
        : "+f"(c[0]), "+f"(c[1]), "+f"(c[2]), "+f"(c[3])
        : "r"(a[0]), "r"(a[1]), "r"(a[2]), "r"(a[3]), "r"(b[0]), "r"(b[1]));
}
__device__ __forceinline__ uint32_t pack_hl(float a, float b, uint32_t& lo_out) {
    __nv_bfloat16 ha = __float2bfloat16(a), hb = __float2bfloat16(b);
    float ra = a - __bfloat162float(ha), rb = b - __bfloat162float(hb);
    __nv_bfloat16 la = __float2bfloat16(ra), lb = __float2bfloat16(rb);
    lo_out = (uint32_t)__bfloat16_as_ushort(la) | ((uint32_t)__bfloat16_as_ushort(lb) << 16);
    return (uint32_t)__bfloat16_as_ushort(ha) | ((uint32_t)__bfloat16_as_ushort(hb) << 16);
}

// warp GEMM, bf16 3-term split. A: rows x ARB bytes (16B chunks swizzled
// c^(r&7)); ck base = kbase. B: local k-rows x BRB bytes. KK k-chunks of 16.
// C has NFT n-frag slots; NF2*2 <= NFT used.
template<int MF, int NF2, int NFT, int ARB, int BRB, int KK>
__device__ __forceinline__ void wgemm(uint32_t aH, uint32_t aL,
                                      uint32_t bH, uint32_t bL,
                                      int m0, int n0, int kbase, int lane,
                                      float C[MF][NFT][4])
{
    for (int kk = 0; kk < KK; kk++) {
        uint32_t ah[MF][4], al[MF][4];
        #pragma unroll
        for (int mf = 0; mf < MF; mf++) {
            int r = m0 + mf * 16 + (lane & 15);
            int ck = kbase + kk * 2 + (lane >> 4);
            uint32_t off = (uint32_t)(r * ARB + ((ck ^ (r & 7)) << 4));
            ldsm4(ah[mf], aH + off);
            ldsm4(al[mf], aL + off);
        }
        int rb = kk * 16 + (lane & 15);
        #pragma unroll
        for (int nf2 = 0; nf2 < NF2; nf2++) {
            int ncq = (n0 >> 3) + nf2 * 2 + (lane >> 4);
            uint32_t boff = (uint32_t)(rb * BRB + ((ncq ^ (rb & 7)) << 4));
            uint32_t bh[4], bl[4];
            ldsm4t(bh, bH + boff);
            ldsm4t(bl, bL + boff);
            #pragma unroll
            for (int mf = 0; mf < MF; mf++) {
                mma16816(C[mf][nf2 * 2], ah[mf], bh);
                mma16816(C[mf][nf2 * 2], al[mf], bh);
                mma16816(C[mf][nf2 * 2], ah[mf], bl);
                mma16816(C[mf][nf2 * 2 + 1], ah[mf], bh + 2);
                mma16816(C[mf][nf2 * 2 + 1], al[mf], bh + 2);
                mma16816(C[mf][nf2 * 2 + 1], ah[mf], bl + 2);
            }
        }
    }
}

// =======================================================================
// MLP
// =======================================================================
__global__ void k_mlp(const float* __restrict__ x,
                      const float* __restrict__ W0, const float* __restrict__ b0,
                      const float* __restrict__ W1, const float* __restrict__ b1,
                      const float* __restrict__ W2, const float* __restrict__ b2)
{
    int mat = blockIdx.y;
    const float* W  = (mat == 0) ? W0 : (mat == 1) ? W1 : W2;
    const float* bb = (mat == 0) ? b0 : (mat == 1) ? b1 : b2;
    float* out = g_P + (size_t)mat * BS * DD;
    int row0 = blockIdx.x * 32;
    const float* A = x + (size_t)row0 * DIN;
    __shared__ float xs[32][32];
    __shared__ float ws[32][128];
    int t = threadIdx.x;
    int cx = t & 31, ry = t >> 5;
    float acc[4][4] = {};
    for (int kc = 0; kc < DIN; kc += 32) {
        #pragma unroll
        for (int u = 0; u < 4; u++) {
            int idx = t + u * 256;
            xs[idx >> 5][idx & 31] = A[(idx >> 5) * DIN + kc + (idx & 31)];
        }
        #pragma unroll
        for (int u = 0; u < 16; u++) {
            int idx = t + u * 256;
            ws[idx >> 7][idx & 127] = W[(kc + (idx >> 7)) * DD + (idx & 127)];
        }
        __syncthreads();
        #pragma unroll
        for (int k = 0; k < 32; k++) {
            float4 wv = *(const float4*)&ws[k][cx * 4];
            #pragma unroll
            for (int m = 0; m < 4; m++) {
                float av = xs[ry * 4 + m][k];
                acc[m][0] += av * wv.x; acc[m][1] += av * wv.y;
                acc[m][2] += av * wv.z; acc[m][3] += av * wv.w;
            }
        }
        __syncthreads();
    }
    float4 bv = *(const float4*)&bb[cx * 4];
    #pragma unroll
    for (int m = 0; m < 4; m++) {
        float4 v;
        v.x = acc[m][0] + bv.x; v.y = acc[m][1] + bv.y;
        v.z = acc[m][2] + bv.z; v.w = acc[m][3] + bv.w;
        v.x = v.x > 0.f ? v.x : 0.1f * v.x;
        v.y = v.y > 0.f ? v.y : 0.1f * v.y;
        v.z = v.z > 0.f ? v.z : 0.1f * v.z;
        v.w = v.w > 0.f ? v.w : 0.1f * v.w;
        *(float4*)&out[(size_t)(row0 + ry * 4 + m) * DD + cx * 4] = v;
    }
}

// =======================================================================
// W prep: 6 weight tensors fp32 -> bf16 hi/lo
// =======================================================================
__global__ void k_wprep6(const float* __restrict__ W0, const float* __restrict__ W1,
                         const float* __restrict__ W2, const float* __restrict__ W3,
                         const float* __restrict__ W4, const float* __restrict__ W5)
{
    int head = blockIdx.y;
    const float* W = (head == 0) ? W0 : (head == 1) ? W1 : (head == 2) ? W2
                   : (head == 3) ? W3 : (head == 4) ? W4 : W5;
    size_t p = (size_t)blockIdx.x * 1024 + threadIdx.x;   // pair idx, 1048576 total
    float2 f = *(const float2*)(W + p * 2);
    uint32_t lo;
    uint32_t hi = pack_hl(f.x, f.y, lo);
    ((uint32_t*)g_W6h[head])[p] = hi;
    ((uint32_t*)g_W6l[head])[p] = lo;
}

// =======================================================================
// Fused prep: g_P[sel][b][y][j] -> Yt (transposed bf16 hi/lo) AND Pb (packed)
// grid (6 ytiles, 4 jtiles, 6 = sel*2+b), block (32,8)
// =======================================================================
__global__ void k_prep()
{
    int sel = blockIdx.z >> 1, b = blockIdx.z & 1;
    int y0 = blockIdx.x * 32, j0 = blockIdx.y * 32;
    const float* src = g_P + (size_t)sel * BS * DD + (size_t)b * SEQ * DD;
    __shared__ float t[32][33];
    int tx = threadIdx.x, ty = threadIdx.y;
    #pragma unroll
    for (int r = 0; r < 4; r++)
        t[ty + r * 8][tx] = src[(size_t)(y0 + ty + r * 8) * DD + j0 + tx];
    __syncthreads();
    #pragma unroll
    for (int r = 0; r < 4; r++) {
        int jj = ty + r * 8, yy = tx;
        float v = t[yy][jj];
        __nv_bfloat16 h = __float2bfloat16(v);
        __nv_bfloat16 l = __float2bfloat16(v - __bfloat162float(h));
        size_t o = (size_t)b * DD * SEQ + (size_t)(j0 + jj) * SEQ + y0 + yy;
        g_Yth[sel][o] = __bfloat16_as_ushort(h);
        g_Ytl[sel][o] = __bfloat16_as_ushort(l);
    }
    // straight pack (coalesced along j)
    #pragma unroll
    for (int r = 0; r < 4; r++) {
        int y = y0 + ty + r * 8, j = j0 + tx;
        float v = t[ty + r * 8][tx];
        __nv_bfloat16 h = __float2bfloat16(v);
        __nv_bfloat16 l = __float2bfloat16(v - __bfloat162float(h));
        size_t o = ((size_t)b * SEQ + y) * DD + j;
        g_Pbh[sel][o] = __bfloat16_as_ushort(h);
        g_Pbl[sel][o] = __bfloat16_as_ushort(l);
    }
}

// =======================================================================
// Stage1: T[h][bz,i,j] = sum_k Z[bz,k] W_h[i,k,j]  (cp.async loads)
// grid (128 i, 3 bz-tiles, 6 heads), 256 threads, 64KB smem, K-chunked
// =======================================================================
#define S1_SMEM 65536
__global__ void __launch_bounds__(256, 2) k_stage1_all()
{
    extern __shared__ __align__(16) char smem[];
    uint32_t sb = smem_to_u32(smem);
    int tid = threadIdx.x, lane = tid & 31, w = tid >> 5;
    int i = blockIdx.x, bz0 = blockIdx.y * 128, head = blockIdx.z;
    int zsel = c_zsel[head];
    const uint4* Zh4 = (const uint4*)g_Pbh[zsel] + (size_t)bz0 * 16;
    const uint4* Zl4 = (const uint4*)g_Pbl[zsel] + (size_t)bz0 * 16;
    const uint4* Wh4 = (const uint4*)g_W6h[head] + (size_t)i * 2048;
    const uint4* Wl4 = (const uint4*)g_W6l[head] + (size_t)i * 2048;

    float C[4][4][4] = {};
    int m0 = (w >> 2) * 64, n0 = (w & 3) * 32;

    for (int kc = 0; kc < 128; kc += 64) {
        __syncthreads();
        for (int idx = tid; idx < 1024; idx += 256) {   // Z: 128 rows x 8 chunks
            int r = idx >> 3, c = idx & 7;
            uint32_t off = (uint32_t)(r * 128 + ((c ^ (r & 7)) << 4));
            int src = r * 16 + (kc >> 3) + c;
            CP_A16(sb + off, Zh4 + src);
            CP_A16(sb + 16384 + off, Zl4 + src);
        }
        for (int idx = tid; idx < 1024; idx += 256) {   // W: 64 k-rows x 16 chunks
            int r = idx >> 4, c = idx & 15;
            uint32_t off = (uint32_t)(r * 256 + ((c ^ (r & 7)) << 4));
            int src = (kc + r) * 16 + c;
            CP_A16(sb + 32768 + off, Wh4 + src);
            CP_A16(sb + 49152 + off, Wl4 + src);
        }
        CP_COMMIT(); CP_WAIT0();
        __syncthreads();
        wgemm<4, 2, 4, 128, 256, 4>(sb, sb + 16384, sb + 32768, sb + 49152,
                                    m0, n0, 0, lane, C);
    }

    uint32_t* TH = (uint32_t*)g_T6h[head];
    uint32_t* TL = (uint32_t*)g_T6l[head];
    #pragma unroll
    for (int mf = 0; mf < 4; mf++)
        #pragma unroll
        for (int nf = 0; nf < 4; nf++) {
            int row = m0 + mf * 16 + (lane >> 2);
            int col = n0 + nf * 8 + (lane & 3) * 2;
            uint32_t lo;
            uint32_t hi = pack_hl(C[mf][nf][0], C[mf][nf][1], lo);
            size_t o = ((size_t)(bz0 + row) * 16384 + (size_t)i * 128 + col) >> 1;
            TH[o] = hi; TL[o] = lo;
            hi = pack_hl(C[mf][nf][2], C[mf][nf][3], lo);
            o = ((size_t)(bz0 + row + 8) * 16384 + (size_t)i * 128 + col) >> 1;
            TH[o] = hi; TL[o] = lo;
        }
}

// =======================================================================
// Fused stage2+3, split-M, Y pipelined: grid (2 ti, 384 bz, 6 head), 256 thr
// smem: XM hi@0(24K) lo@24576 ; T hi@49152(32K) lo@81920
//       stage3: Y dbl-buffer @49152 (2 x (12K hi + 12K lo)); Ssm 96x193 @0
// =======================================================================
#define XM_H 0
#define XM_L 24576
#define TB_H 49152
#define TB_L 81920
#define YB0  49152
#define S23_SMEM 114688
__global__ void __launch_bounds__(256, 2) k_stage23_all(float* __restrict__ out)
{
    extern __shared__ __align__(16) char smem[];
    uint32_t sb = smem_to_u32(smem);
    int tid = threadIdx.x, lane = tid & 31, w = tid >> 5;
    int ti = blockIdx.x, bz = blockIdx.y, head = blockIdx.z, b = bz / SEQ;
    int xsel = c_xsel[head], ysel = c_ysel[head], dosym = c_sym[head];
    bool narrow = dosym && (ti == 1);

    // ---- async load X rows [ti*96,+96) and T (128x128) ----
    const uint4* Xh4 = (const uint4*)g_Pbh[xsel] + ((size_t)b * SEQ + ti * 96) * 16;
    const uint4* Xl4 = (const uint4*)g_Pbl[xsel] + ((size_t)b * SEQ + ti * 96) * 16;
    const uint4* TH4 = (const uint4*)(g_T6h[head] + (size_t)bz * DD * DD);
    const uint4* TL4 = (const uint4*)(g_T6l[head] + (size_t)bz * DD * DD);
    for (int idx = tid; idx < 1536; idx += 256) {
        int r = idx >> 4, c = idx & 15;
        uint32_t off = (uint32_t)(r * 256 + ((c ^ (r & 7)) << 4));
        CP_A16(sb + XM_H + off, Xh4 + idx);
        CP_A16(sb + XM_L + off, Xl4 + idx);
    }
    for (int idx = tid; idx < 2048; idx += 256) {
        int r = idx >> 4, c = idx & 15;
        uint32_t off = (uint32_t)(r * 256 + ((c ^ (r & 7)) << 4));
        CP_A16(sb + TB_H + off, TH4 + idx);
        CP_A16(sb + TB_L + off, TL4 + idx);
    }
    CP_COMMIT(); CP_WAIT0();
    __syncthreads();

    // ---- stage2: M1 = X @ T  (8 warps, tile 48x32) ----
    {
        float C2[3][4][4] = {};
        int m0 = (w >> 2) * 48, n0 = (w & 3) * 32;
        wgemm<3, 2, 4, 256, 256, 8>(sb + XM_H, sb + XM_L, sb + TB_H, sb + TB_L,
                                    m0, n0, 0, lane, C2);
        __syncthreads();
        #pragma unroll
        for (int mf = 0; mf < 3; mf++)
            #pragma unroll
            for (int nf = 0; nf < 4; nf++) {
                int row = m0 + mf * 16 + (lane >> 2);
                int col = n0 + nf * 8 + (lane & 3) * 2;
                uint32_t lo0, lo1;
                uint32_t hi0 = pack_hl(C2[mf][nf][0], C2[mf][nf][1], lo0);
                uint32_t hi1 = pack_hl(C2[mf][nf][2], C2[mf][nf][3], lo1);
                int r2 = row + 8;
                uint32_t o0 = (uint32_t)(row * 256 + (((col >> 3) ^ (row & 7)) << 4) + (col & 7) * 2);
                uint32_t o1 = (uint32_t)(r2 * 256 + (((col >> 3) ^ (r2 & 7)) << 4) + (col & 7) * 2);
                *(uint32_t*)(smem + XM_H + o0) = hi0;
                *(uint32_t*)(smem + XM_L + o0) = lo0;
                *(uint32_t*)(smem + XM_H + o1) = hi1;
                *(uint32_t*)(smem + XM_L + o1) = lo1;
            }
    }
    __syncthreads();

    // ---- stage3: S = M1 @ Y^T, 4 pipelined 32-j-row chunks ----
    int m3, n3, nfmax; bool act;
    if (!narrow) { m3 = (w >> 2) * 48; n3 = (w & 3) * 48; nfmax = 6; act = true; }
    else         { act = (w < 6); m3 = (w / 3) * 48; n3 = 96 + (w % 3) * 32; nfmax = 4; }

    const uint4* YH4 = (const uint4*)(g_Yth[ysel] + (size_t)b * DD * SEQ);
    const uint4* YL4 = (const uint4*)(g_Ytl[ysel] + (size_t)b * DD * SEQ);
    auto loadY = [&](int jc) {
        uint32_t base = sb + YB0 + (uint32_t)(jc & 1) * 24576;
        for (int idx = tid; idx < 768; idx += 256) {
            int r = idx / 24, c = idx % 24;
            uint32_t off = (uint32_t)(r * 384 + ((c ^ (r & 7)) << 4));
            int src = (jc * 32 + r) * 24 + c;
            CP_A16(base + off, YH4 + src);
            CP_A16(base + 12288 + off, YL4 + src);
        }
        CP_COMMIT();
    };

    float C3[3][6][4] = {};
    loadY(0);
    for (int jc = 0; jc < 4; jc++) {
        if (jc < 3) { loadY(jc + 1); CP_WAIT1(); }
        else        { CP_WAIT0(); }
        __syncthreads();
        uint32_t yb = sb + YB0 + (uint32_t)(jc & 1) * 24576;
        if (act) {
            if (!narrow)
                wgemm<3, 3, 6, 256, 384, 2>(sb + XM_H, sb + XM_L, yb, yb + 12288,
                                            m3, n3, jc * 4, lane, C3);
            else
                wgemm<3, 2, 6, 256, 384, 2>(sb + XM_H, sb + XM_L, yb, yb + 12288,
                                            m3, n3, jc * 4, lane, C3);
        }
        __syncthreads();
    }

    // ---- epilogue: frags -> Ssm (96 x stride 193), folded writes ----
    float* Ssm = (float*)smem;
    if (act) {
        #pragma unroll
        for (int mf = 0; mf < 3; mf++)
            for (int nf = 0; nf < nfmax; nf++) {
                int row = m3 + mf * 16 + (lane >> 2);
                int col = n3 + nf * 8 + (lane & 3) * 2;
                Ssm[row * 193 + col]           = C3[mf][nf][0];
                Ssm[row * 193 + col + 1]       = C3[mf][nf][1];
                Ssm[(row + 8) * 193 + col]     = C3[mf][nf][2];
                Ssm[(row + 8) * 193 + col + 1] = C3[mf][nf][3];
            }
    }
    __syncthreads();

    float* dst = (head < 4) ? (out + (size_t)head * OUTW) : g_S2[head - 4];
    dst += (size_t)bz * N2;

    if (!dosym) {
        for (int idx = tid * 4; idx < 96 * SEQ; idx += 1024) {
            int r = idx / SEQ, y = idx % SEQ;
            float4 v = make_float4(Ssm[r * 193 + y],     Ssm[r * 193 + y + 1],
                                   Ssm[r * 193 + y + 2], Ssm[r * 193 + y + 3]);
            *(float4*)(dst + (size_t)(ti * 96 + r) * SEQ + y) = v;
        }
    } else if (ti == 0) {
        for (int idx = tid * 4; idx < 96 * SEQ; idx += 1024) {
            int r = idx / SEQ, y = idx % SEQ;
            float4 v;
            v.x = (r <= y)     ? Ssm[r * 193 + y]     : Ssm[y * 193 + r];
            v.y = (r <= y + 1) ? Ssm[r * 193 + y + 1] : Ssm[(y + 1) * 193 + r];
            v.z = (r <= y + 2) ? Ssm[r * 193 + y + 2] : Ssm[(y + 2) * 193 + r];
            v.w = (r <= y + 3) ? Ssm[r * 193 + y + 3] : Ssm[(y + 3) * 193 + r];
            *(float4*)(dst + (size_t)r * SEQ + y) = v;
        }
        for (int idx = tid * 4; idx < 96 * 96; idx += 1024) {
            int r2 = idx / 96, c2 = idx % 96;
            float4 v = make_float4(Ssm[c2 * 193 + 96 + r2],
                                   Ssm[(c2 + 1) * 193 + 96 + r2],
                                   Ssm[(c2 + 2) * 193 + 96 + r2],
                                   Ssm[(c2 + 3) * 193 + 96 + r2]);
            *(float4*)(dst + (size_t)(96 + r2) * SEQ + c2) = v;
        }
    } else {
        for (int idx = tid * 4; idx < 96 * 96; idx += 1024) {
            int r = idx / 96, c = idx % 96;
            float4 v;
            v.x = (r <= c)     ? Ssm[r * 193 + 96 + c]     : Ssm[c * 193 + 96 + r];
            v.y = (r <= c + 1) ? Ssm[r * 193 + 96 + c + 1] : Ssm[(c + 1) * 193 + 96 + r];
            v.z = (r <= c + 2) ? Ssm[r * 193 + 96 + c + 2] : Ssm[(c + 2) * 193 + 96 + r];
            v.w = (r <= c + 3) ? Ssm[r * 193 + 96 + c + 3] : Ssm[(c + 3) * 193 + 96 + r];
            *(float4*)(dst + (size_t)(96 + r) * SEQ + 96 + c) = v;
        }
    }
}

// =======================================================================
// Permute (0,2,3,1): out[b, q=x*S+y, z] = g_S2[hs][b, z, q]
// =======================================================================
__global__ void k_perm(float* __restrict__ out)
{
    int hs = blockIdx.z >> 1, b = blockIdx.z & 1;
    const float* in = g_S2[hs] + (size_t)b * N3;
    float* o = out + (size_t)(4 + hs) * OUTW + (size_t)b * N3;
    int q0 = blockIdx.x * 32, z0 = blockIdx.y * 32;
    __shared__ float tile[32][33];
    int tx = threadIdx.x, ty = threadIdx.y;
    #pragma unroll
    for (int r = 0; r < 4; r++)
        tile[ty + r * 8][tx] = in[(size_t)(z0 + ty + r * 8) * N2 + q0 + tx];
    __syncthreads();
    #pragma unroll
    for (int r = 0; r < 4; r++)
        o[(size_t)(q0 + ty + r * 8) * SEQ + z0 + tx] = tile[tx][ty + r * 8];
}

// =======================================================================
extern "C" void kernel_launch(void* const* d_in, const int* in_sizes, int n_in,
                              void* d_out, int out_size)
{
    const float* x  = (const float*)d_in[0];
    const float* Wp = (const float*)d_in[1];
    const float* bp = (const float*)d_in[2];
    const float* Wh = (const float*)d_in[3];
    const float* bh = (const float*)d_in[4];
    const float* Wt = (const float*)d_in[5];
    const float* bt = (const float*)d_in[6];
    float* out = (float*)d_out;

    cudaFuncSetAttribute(k_stage1_all,  cudaFuncAttributeMaxDynamicSharedMemorySize, S1_SMEM);
    cudaFuncSetAttribute(k_stage23_all, cudaFuncAttributeMaxDynamicSharedMemorySize, S23_SMEM);

    k_wprep6<<<dim3(1024, 6), 1024>>>(
        (const float*)d_in[7],  (const float*)d_in[8],  (const float*)d_in[9],
        (const float*)d_in[10], (const float*)d_in[11], (const float*)d_in[12]);
    k_mlp<<<dim3(12, 3), 256>>>(x, Wp, bp, Wh, bh, Wt, bt);
    k_prep<<<dim3(6, 4, 6), dim3(32, 8)>>>();
    k_stage1_all<<<dim3(128, 3, 6), 256, S1_SMEM>>>();
    k_stage23_all<<<dim3(2, 384, 6), 256, S23_SMEM>>>(out);
    k_perm<<<dim3(1152, 6, 4), dim3(32, 8)>>>(out);
}